// round 9
// baseline (speedup 1.0000x reference)
#include <cuda_runtime.h>
#include <math.h>
#include <stdint.h>

// ---------------- problem-size bounds (N=50000, E=400000 in dataset) ----------
#define MAXN 50176
#define MAXE 400384

// ---------------- device scratch (no mallocs allowed) -------------------------
__device__ float  g_h1  [MAXN * 128];            // layer1 node embeddings [N,4,32]
__device__ float  g_res [MAXN * 128];            // residual (res1 then res2)
__device__ float  g_acc1[MAXN * 128];            // layer1 aggregate -> y -> BN input
__device__ float  g_h2  [(size_t)MAXN * 512];    // layer2 node embeddings [N,4,128]
__device__ float  g_acc2[MAXN * 128];            // layer2 head-averaged aggregate
__device__ float  g_s[MAXN * 4], g_d[MAXN * 4];  // attention src/dst terms
__device__ float  g_den[MAXN * 4];
__device__ float  g_alpha[MAXE * 4];             // layer2 ex values
__device__ float  g_e2[MAXE * 4];                // layer2 edge attention term
__device__ double g_colsum[128], g_colsq[128];
__device__ float  g_aew1T[4 * 64], g_aew2T[4 * 64];  // transposed [h][k]
__device__ float  g_eea1[4 * 4],  g_eea2[4 * 4];
__device__ float  g_ne1w1[3 * 128], g_ne2w2[3 * 512];

// ---------------- helpers ------------------------------------------------------
__device__ __forceinline__ void red4(float* p, float a, float b, float c, float d) {
    asm volatile("red.global.add.v4.f32 [%0], {%1,%2,%3,%4};"
                 :: "l"(p), "f"(a), "f"(b), "f"(c), "f"(d) : "memory");
}

// Packed fp32x2 FMA (sm_100+): acc.lo += a.lo*b.lo; acc.hi += a.hi*b.hi (exact fp32)
__device__ __forceinline__ void ffma2(uint64_t& acc, uint64_t a, uint64_t b) {
    asm volatile("fma.rn.f32x2 %0, %1, %2, %0;" : "+l"(acc) : "l"(a), "l"(b));
}
__device__ __forceinline__ uint64_t pack2(float x, float y) {
    uint64_t r; asm("mov.b64 %0, {%1, %2};" : "=l"(r) : "f"(x), "f"(y)); return r;
}
__device__ __forceinline__ float2 unpack2(uint64_t v) {
    float2 r; asm("mov.b64 {%0, %1}, %2;" : "=f"(r.x), "=f"(r.y) : "l"(v)); return r;
}

// ---------------- precompute: fold linear maps (+ zero colsum) ------------------
__global__ void k_pre_a(const float* __restrict__ we1, const float* __restrict__ aedge1,
                        const float* __restrict__ we2, const float* __restrict__ aedge2,
                        const float* __restrict__ ne1, const float* __restrict__ w1,
                        const float* __restrict__ ne2, const float* __restrict__ w2) {
    int i = blockIdx.x * blockDim.x + threadIdx.x;
    if (i < 128) { g_colsum[i] = 0.0; g_colsq[i] = 0.0; }
    if (i < 256) {                       // aeW1^T: [4][64], C=32
        int k = i >> 2, h = i & 3; float a = 0.f;
        for (int c = 0; c < 32; c++) a += we1[k * 128 + h * 32 + c] * aedge1[h * 32 + c];
        g_aew1T[h * 64 + k] = a;
    } else if (i < 512) {                // aeW2^T: [4][64], C=128
        int j = i - 256; int k = j >> 2, h = j & 3; float a = 0.f;
        for (int c = 0; c < 128; c++) a += we2[k * 512 + h * 128 + c] * aedge2[h * 128 + c];
        g_aew2T[h * 64 + k] = a;
    } else if (i < 896) {                // ne1@w1: [3,128]
        int j = i - 512; int t = j >> 7, col = j & 127; float a = 0.f;
        for (int k = 0; k < 32; k++) a += ne1[t * 32 + k] * w1[k * 128 + col];
        g_ne1w1[j] = a;
    } else if (i < 2432) {               // ne2@w2: [3,512]
        int j = i - 896; int t = j >> 9, col = j & 511; float a = 0.f;
        for (int k = 0; k < 128; k++) a += ne2[t * 128 + k] * w2[k * 512 + col];
        g_ne2w2[j] = a;
    }
}

__global__ void k_pre_b(const float* __restrict__ ee1, const float* __restrict__ ee2) {
    int i = threadIdx.x;
    if (i < 16) {
        int t = i >> 2, h = i & 3; float a = 0.f;
        for (int k = 0; k < 64; k++) a += ee1[t * 64 + k] * g_aew1T[h * 64 + k];
        g_eea1[i] = a;
    } else if (i < 32) {
        int j = i - 16; int t = j >> 2, h = j & 3; float a = 0.f;
        for (int k = 0; k < 64; k++) a += ee2[t * 64 + k] * g_aew2T[h * 64 + k];
        g_eea2[j] = a;
    }
}

// ---------------- layer 1 GEMM: 128-row tile, ct on blockIdx.y, fused sd1/zeroing -
__global__ void __launch_bounds__(256, 2)
k_gemm1(const float* __restrict__ x, const int* __restrict__ nt,
        const float* __restrict__ w1, const float* __restrict__ wres1,
        const float* __restrict__ b1,
        const float* __restrict__ asrc, const float* __restrict__ adst, int N) {
    __shared__ __align__(16) float sXT[32][132];   // [k][r]
    __shared__ __align__(16) float sW[32][132];    // [k][c]
    __shared__ float sA[128], sD[128];
    int t = threadIdx.x;           // 256
    int r0 = blockIdx.x * 128;
    int ct = blockIdx.y;           // 0: w1 + sd dots, 1: wres1 + acc zeroing
    int tc = t & 15, tr = t >> 4;

    for (int i = t; i < 128 * 32; i += 256) {
        int r = i >> 5, k = i & 31;
        int gr = r0 + r;
        sXT[k][r] = (gr < N) ? x[(size_t)gr * 32 + k] : 0.f;
    }
    if (ct == 0 && t < 128) { sA[t] = asrc[t]; sD[t] = adst[t]; }
    {
        const float* wp = ct ? wres1 : w1;
        for (int i = t; i < 32 * 32; i += 256) {
            int k = i >> 5, c4 = i & 31;
            *reinterpret_cast<float4*>(&sW[k][c4 * 4]) =
                *reinterpret_cast<const float4*>(&wp[k * 128 + c4 * 4]);
        }
    }
    __syncthreads();

    uint64_t acc[8][4];
    #pragma unroll
    for (int j = 0; j < 8; j++)
        #pragma unroll
        for (int p = 0; p < 4; p++) acc[j][p] = 0ull;

    #pragma unroll 8
    for (int k = 0; k < 32; k++) {
        float4 xa = *reinterpret_cast<const float4*>(&sXT[k][tr * 8]);
        float4 xb = *reinterpret_cast<const float4*>(&sXT[k][tr * 8 + 4]);
        ulonglong2 wa = *reinterpret_cast<const ulonglong2*>(&sW[k][tc * 8]);
        ulonglong2 wb = *reinterpret_cast<const ulonglong2*>(&sW[k][tc * 8 + 4]);
        float xs[8] = {xa.x, xa.y, xa.z, xa.w, xb.x, xb.y, xb.z, xb.w};
        #pragma unroll
        for (int j = 0; j < 8; j++) {
            uint64_t x2 = pack2(xs[j], xs[j]);
            ffma2(acc[j][0], x2, wa.x);
            ffma2(acc[j][1], x2, wa.y);
            ffma2(acc[j][2], x2, wb.x);
            ffma2(acc[j][3], x2, wb.y);
        }
    }

    if (ct == 0) {
        float av[8], dv[8];
        #pragma unroll
        for (int i = 0; i < 8; i++) { av[i] = sA[tc * 8 + i]; dv[i] = sD[tc * 8 + i]; }
        int head = tc >> 2;
        #pragma unroll
        for (int j = 0; j < 8; j++) {
            int gr = r0 + tr * 8 + j;
            float o[8];
            #pragma unroll
            for (int p = 0; p < 4; p++) {
                float2 u = unpack2(acc[j][p]);
                o[2 * p] = u.x; o[2 * p + 1] = u.y;
            }
            int ty = (gr < N) ? nt[gr] : 0;
            const float* bias = &g_ne1w1[ty * 128 + tc * 8];
            float sp = 0.f, dp = 0.f;
            #pragma unroll
            for (int i = 0; i < 8; i++) {
                o[i] += bias[i];
                sp += o[i] * av[i];
                dp += o[i] * dv[i];
            }
            sp += __shfl_xor_sync(0xffffffffu, sp, 1);
            sp += __shfl_xor_sync(0xffffffffu, sp, 2);
            dp += __shfl_xor_sync(0xffffffffu, dp, 1);
            dp += __shfl_xor_sync(0xffffffffu, dp, 2);
            if (gr < N) {
                float* dst = &g_h1[(size_t)gr * 128 + tc * 8];
                *reinterpret_cast<float4*>(dst)     = make_float4(o[0], o[1], o[2], o[3]);
                *reinterpret_cast<float4*>(dst + 4) = make_float4(o[4], o[5], o[6], o[7]);
                if ((tc & 3) == 0) {
                    g_s[gr * 4 + head] = sp; g_d[gr * 4 + head] = dp;
                    g_den[gr * 4 + head] = 0.f;
                }
            }
        }
    } else {
        float bb[8];
        #pragma unroll
        for (int i = 0; i < 8; i++) bb[i] = b1[tc * 8 + i];
        float4 z4 = make_float4(0.f, 0.f, 0.f, 0.f);
        #pragma unroll
        for (int j = 0; j < 8; j++) {
            int gr = r0 + tr * 8 + j; if (gr >= N) continue;
            float o[8];
            #pragma unroll
            for (int p = 0; p < 4; p++) {
                float2 u = unpack2(acc[j][p]);
                o[2 * p] = u.x; o[2 * p + 1] = u.y;
            }
            float* dst = &g_res[(size_t)gr * 128 + tc * 8];
            *reinterpret_cast<float4*>(dst) =
                make_float4(o[0] + bb[0], o[1] + bb[1], o[2] + bb[2], o[3] + bb[3]);
            *reinterpret_cast<float4*>(dst + 4) =
                make_float4(o[4] + bb[4], o[5] + bb[5], o[6] + bb[6], o[7] + bb[7]);
            float* az = &g_acc1[(size_t)gr * 128 + tc * 8];
            *reinterpret_cast<float4*>(az)     = z4;
            *reinterpret_cast<float4*>(az + 4) = z4;
        }
    }
}

// ---------------- layer 1 fused edge phase v3: looped, register-hoisted weights ---
// 4 edges per warp-iteration, 8 lanes/edge; weights loaded once per thread.
__global__ void __launch_bounds__(256)
k_edge1(const int* __restrict__ src, const int* __restrict__ dst,
        const float* __restrict__ ea, const int* __restrict__ et, int E) {
    __shared__ float se1[16], se2[16];
    int t = threadIdx.x;  // 256
    if (t < 16) { se1[t] = g_eea1[t]; se2[t] = g_eea2[t]; }
    __syncthreads();
    int l = t & 31, li = l & 7, sub = l >> 3;

    // hoist attention-weight slices into registers (once per thread)
    float wa[4][8], wb[4][8];
    #pragma unroll
    for (int h = 0; h < 4; h++)
        #pragma unroll
        for (int j = 0; j < 8; j++) {
            wa[h][j] = g_aew1T[h * 64 + li * 8 + j];
            wb[h][j] = g_aew2T[h * 64 + li * 8 + j];
        }

    int warpId = blockIdx.x * 8 + (t >> 5);
    int nWarps = gridDim.x * 8;
    int stride = nWarps * 4;

    for (int eBase = warpId * 4; eBase < E; eBase += stride) {
        int e = eBase + sub;
        bool valid = e < E;
        float e1[4] = {0, 0, 0, 0}, e2[4] = {0, 0, 0, 0};
        int s_ = 0, d_ = 0;
        if (valid) {
            s_ = src[e]; d_ = dst[e];
            const float* row = ea + (size_t)e * 64 + li * 8;
            float4 va = *reinterpret_cast<const float4*>(row);
            float4 vb = *reinterpret_cast<const float4*>(row + 4);
            float vs[8] = {va.x, va.y, va.z, va.w, vb.x, vb.y, vb.z, vb.w};
            #pragma unroll
            for (int h = 0; h < 4; h++) {
                float a1 = 0.f, a2 = 0.f;
                #pragma unroll
                for (int j = 0; j < 8; j++) {
                    a1 += vs[j] * wa[h][j];
                    a2 += vs[j] * wb[h][j];
                }
                e1[h] = a1; e2[h] = a2;
            }
        }
        #pragma unroll
        for (int h = 0; h < 4; h++)
            #pragma unroll
            for (int o = 1; o < 8; o <<= 1) {
                e1[h] += __shfl_xor_sync(0xffffffffu, e1[h], o);
                e2[h] += __shfl_xor_sync(0xffffffffu, e2[h], o);
            }
        float ex = 0.f;
        if (valid && li < 4) {
            float ev1 = (li == 0) ? e1[0] : (li == 1) ? e1[1] : (li == 2) ? e1[2] : e1[3];
            float ev2 = (li == 0) ? e2[0] : (li == 1) ? e2[1] : (li == 2) ? e2[2] : e2[3];
            int ty = et[e];
            float a = g_s[s_ * 4 + li] + g_d[d_ * 4 + li] + ev1 + se1[ty * 4 + li];
            a = (a >= 0.f) ? a : 0.2f * a;
            ex = __expf(a);
            atomicAdd(&g_den[d_ * 4 + li], ex);
            g_e2[e * 4 + li] = ev2 + se2[ty * 4 + li];
        }
        float exh = __shfl_sync(0xffffffffu, ex, (l & 24) + (li >> 1));
        if (valid) {
            const float4* hb = reinterpret_cast<const float4*>(&g_h1[(size_t)s_ * 128 + li * 16]);
            float* ab = &g_acc1[(size_t)d_ * 128 + li * 16];
            #pragma unroll
            for (int j = 0; j < 4; j++) {
                float4 v = hb[j];
                red4(ab + j * 4, v.x * exh, v.y * exh, v.z * exh, v.w * exh);
            }
        }
    }
}

// ---------------- BN stats: y = acc1/den + res (softmax norm fused) --------------
__global__ void k_bnstats(int N) {
    int t = threadIdx.x;  // 128
    int hh = t >> 5;
    double s = 0.0, q = 0.0;
    for (int n = blockIdx.x; n < N; n += gridDim.x) {
        float den = g_den[n * 4 + hh] + 1e-16f;
        float y = g_acc1[(size_t)n * 128 + t] / den + g_res[(size_t)n * 128 + t];
        g_acc1[(size_t)n * 128 + t] = y;
        s += y; q += (double)y * y;
    }
    atomicAdd(&g_colsum[t], s);
    atomicAdd(&g_colsq[t], q);
}

// ---------------- layer 2 GEMM: ct on blockIdx.y, fused BN-finalize/sd2/zeroing ---
__global__ void __launch_bounds__(256, 2)
k_gemm2(const int* __restrict__ nt, const float* __restrict__ w2,
        const float* __restrict__ wres2, const float* __restrict__ b2,
        const float* __restrict__ asrc, const float* __restrict__ adst,
        const float* __restrict__ gamma, const float* __restrict__ beta, int N) {
    extern __shared__ __align__(16) float sm[];
    float* sXT = sm;               // [k:128][r:132 pad]  (BN applied)
    float* sW  = sm + 128 * 132;   // [k:64][c:132 pad]
    float* sScale = sm + 128 * 132 + 64 * 132;
    float* sShift = sScale + 128;
    int t = threadIdx.x;           // 256
    int r0 = blockIdx.x * 128;
    int ct = blockIdx.y;           // 0..3: w2 col-tiles (+sd dots), 4: wres2 (+zeroing)
    int tc = t & 15, tr = t >> 4;

    if (t < 128) {                 // BN finalize (per block, cheap)
        double mu = g_colsum[t] / N;
        double var = g_colsq[t] / N - mu * mu;
        double sc = (double)gamma[t] / sqrt(var + 1e-5);
        sScale[t] = (float)sc;
        sShift[t] = (float)((double)beta[t] - mu * sc);
    }
    __syncthreads();

    for (int i = t; i < 128 * 128; i += 256) {
        int r = i >> 7, k = i & 127; int gr = r0 + r;
        float v = 0.f;
        if (gr < N) v = g_acc1[(size_t)gr * 128 + k] * sScale[k] + sShift[k];
        sXT[k * 132 + r] = v;
    }

    uint64_t acc[8][4];
    #pragma unroll
    for (int j = 0; j < 8; j++)
        #pragma unroll
        for (int p = 0; p < 4; p++) acc[j][p] = 0ull;

    for (int kh = 0; kh < 2; kh++) {
        __syncthreads();
        for (int i = t; i < 64 * 32; i += 256) {
            int k = i >> 5, c4 = i & 31;
            float4 wv;
            if (ct < 4) wv = *reinterpret_cast<const float4*>(
                             &w2[(size_t)(kh * 64 + k) * 512 + ct * 128 + c4 * 4]);
            else        wv = *reinterpret_cast<const float4*>(
                             &wres2[(size_t)(kh * 64 + k) * 128 + c4 * 4]);
            *reinterpret_cast<float4*>(&sW[k * 132 + c4 * 4]) = wv;
        }
        __syncthreads();

        const float* xbase = sXT + kh * 64 * 132 + tr * 8;
        const float* wbase = sW + tc * 8;
        #pragma unroll 4
        for (int k = 0; k < 64; k++) {
            float4 xa = *reinterpret_cast<const float4*>(xbase + k * 132);
            float4 xb = *reinterpret_cast<const float4*>(xbase + k * 132 + 4);
            ulonglong2 wa = *reinterpret_cast<const ulonglong2*>(wbase + k * 132);
            ulonglong2 wb = *reinterpret_cast<const ulonglong2*>(wbase + k * 132 + 4);
            float xs[8] = {xa.x, xa.y, xa.z, xa.w, xb.x, xb.y, xb.z, xb.w};
            #pragma unroll
            for (int j = 0; j < 8; j++) {
                uint64_t x2 = pack2(xs[j], xs[j]);
                ffma2(acc[j][0], x2, wa.x);
                ffma2(acc[j][1], x2, wa.y);
                ffma2(acc[j][2], x2, wb.x);
                ffma2(acc[j][3], x2, wb.y);
            }
        }
    }

    if (ct < 4) {
        float av[8], dv[8];
        #pragma unroll
        for (int i = 0; i < 8; i++) {
            av[i] = asrc[ct * 128 + tc * 8 + i];
            dv[i] = adst[ct * 128 + tc * 8 + i];
        }
        #pragma unroll
        for (int j = 0; j < 8; j++) {
            int gr = r0 + tr * 8 + j;
            float o[8];
            #pragma unroll
            for (int p = 0; p < 4; p++) {
                float2 u = unpack2(acc[j][p]);
                o[2 * p] = u.x; o[2 * p + 1] = u.y;
            }
            int ty = (gr < N) ? nt[gr] : 0;
            const float* bias = &g_ne2w2[ty * 512 + ct * 128 + tc * 8];
            float sp = 0.f, dp = 0.f;
            #pragma unroll
            for (int i = 0; i < 8; i++) {
                o[i] += bias[i];
                sp += o[i] * av[i];
                dp += o[i] * dv[i];
            }
            #pragma unroll
            for (int off = 8; off; off >>= 1) {
                sp += __shfl_xor_sync(0xffffffffu, sp, off);
                dp += __shfl_xor_sync(0xffffffffu, dp, off);
            }
            if (gr < N) {
                float* dst = &g_h2[(size_t)gr * 512 + ct * 128 + tc * 8];
                *reinterpret_cast<float4*>(dst)     = make_float4(o[0], o[1], o[2], o[3]);
                *reinterpret_cast<float4*>(dst + 4) = make_float4(o[4], o[5], o[6], o[7]);
                if (tc == 0) {
                    g_s[gr * 4 + ct] = sp; g_d[gr * 4 + ct] = dp;
                    g_den[gr * 4 + ct] = 0.f;
                }
            }
        }
    } else {
        float4 z4 = make_float4(0.f, 0.f, 0.f, 0.f);
        #pragma unroll
        for (int j = 0; j < 8; j++) {
            int gr = r0 + tr * 8 + j; if (gr >= N) continue;
            float o[8];
            #pragma unroll
            for (int p = 0; p < 4; p++) {
                float2 u = unpack2(acc[j][p]);
                o[2 * p] = u.x; o[2 * p + 1] = u.y;
            }
            const float* bias = &b2[tc * 8];
            float* dst = &g_res[(size_t)gr * 128 + tc * 8];
            *reinterpret_cast<float4*>(dst) =
                make_float4(o[0] + bias[0], o[1] + bias[1], o[2] + bias[2], o[3] + bias[3]);
            *reinterpret_cast<float4*>(dst + 4) =
                make_float4(o[4] + bias[4], o[5] + bias[5], o[6] + bias[6], o[7] + bias[7]);
            float* az = &g_acc2[(size_t)gr * 128 + tc * 8];
            *reinterpret_cast<float4*>(az)     = z4;
            *reinterpret_cast<float4*>(az + 4) = z4;
        }
    }
}

// ---------------- layer 2 edge pass A: alpha -> ex -> den (no max-sub) ------------
__global__ void k_edge2A(const int* __restrict__ src, const int* __restrict__ dst, int E) {
    int i = blockIdx.x * blockDim.x + threadIdx.x;
    if (i >= E * 4) return;
    int e = i >> 2, h = i & 3;
    int s_ = src[e], d_ = dst[e];
    float a = g_s[s_ * 4 + h] + g_d[d_ * 4 + h] + g_e2[i];
    a = (a >= 0.f) ? a : 0.2f * a;
    float ex = __expf(a);
    g_alpha[i] = ex;
    atomicAdd(&g_den[d_ * 4 + h], ex);
}

// ---------------- edge aggregate layer 2 (head-mean fused) -------------------------
__global__ void k_aggr2(const int* __restrict__ src, const int* __restrict__ dst, int E) {
    int e = blockIdx.x * 8 + (threadIdx.x >> 5); if (e >= E) return;
    int l = threadIdx.x & 31;
    int s_ = src[e], d_ = dst[e];
    float cf = 0.f;
    if (l < 4) cf = 0.25f * g_alpha[e * 4 + l] / (g_den[d_ * 4 + l] + 1e-16f);
    float c0 = __shfl_sync(0xffffffffu, cf, 0);
    float c1 = __shfl_sync(0xffffffffu, cf, 1);
    float c2 = __shfl_sync(0xffffffffu, cf, 2);
    float c3 = __shfl_sync(0xffffffffu, cf, 3);
    const float4* hs = reinterpret_cast<const float4*>(&g_h2[(size_t)s_ * 512]);
    float4 h0 = hs[l], h1 = hs[32 + l], h2v = hs[64 + l], h3 = hs[96 + l];
    float mx = c0 * h0.x + c1 * h1.x + c2 * h2v.x + c3 * h3.x;
    float my = c0 * h0.y + c1 * h1.y + c2 * h2v.y + c3 * h3.y;
    float mz = c0 * h0.z + c1 * h1.z + c2 * h2v.z + c3 * h3.z;
    float mw = c0 * h0.w + c1 * h1.w + c2 * h2v.w + c3 * h3.w;
    red4(&g_acc2[(size_t)d_ * 128 + l * 4], mx, my, mz, mw);
}

// ---------------- final: out = acc2 + res2 -----------------------------------------
__global__ void k_final(float4* __restrict__ out, int N) {
    int i = blockIdx.x * blockDim.x + threadIdx.x;
    if (i >= N * 32) return;
    const float4 a = reinterpret_cast<const float4*>(g_acc2)[i];
    const float4 r = reinterpret_cast<const float4*>(g_res)[i];
    out[i] = make_float4(a.x + r.x, a.y + r.y, a.z + r.z, a.w + r.w);
}

// ---------------- host launch ----------------------------------------------------
extern "C" void kernel_launch(void* const* d_in, const int* in_sizes, int n_in,
                              void* d_out, int out_size) {
    const float* x      = (const float*)d_in[0];
    const int*   ei     = (const int*)  d_in[1];
    const int*   nt     = (const int*)  d_in[2];
    const float* ea     = (const float*)d_in[3];
    const int*   et     = (const int*)  d_in[4];
    const float* ne1    = (const float*)d_in[5];
    const float* w1     = (const float*)d_in[6];
    const float* we1    = (const float*)d_in[7];
    const float* asrc1  = (const float*)d_in[8];
    const float* adst1  = (const float*)d_in[9];
    const float* aedge1 = (const float*)d_in[10];
    const float* ee1    = (const float*)d_in[11];
    const float* wres1  = (const float*)d_in[12];
    const float* b1     = (const float*)d_in[13];
    const float* gamma  = (const float*)d_in[14];
    const float* beta   = (const float*)d_in[15];
    const float* ne2    = (const float*)d_in[16];
    const float* w2     = (const float*)d_in[17];
    const float* we2    = (const float*)d_in[18];
    const float* asrc2  = (const float*)d_in[19];
    const float* adst2  = (const float*)d_in[20];
    const float* aedge2 = (const float*)d_in[21];
    const float* ee2    = (const float*)d_in[22];
    const float* wres2  = (const float*)d_in[23];
    const float* b2     = (const float*)d_in[24];

    int N = in_sizes[0] / 32;
    int E = in_sizes[4];
    const int* src = ei;
    const int* dstp = ei + E;

    // ---- precompute (also zeros colsum/colsq) ----
    k_pre_a<<<10, 256>>>(we1, aedge1, we2, aedge2, ne1, w1, ne2, w2);
    k_pre_b<<<1, 32>>>(ee1, ee2);

    // ---- layer 1 (gemm1 zeros acc1/den) ----
    dim3 g1((N + 127) / 128, 2);
    k_gemm1<<<g1, 256>>>(x, nt, w1, wres1, b1, asrc1, adst1, N);
    k_edge1<<<1024, 256>>>(src, dstp, ea, et, E);

    // ---- batch norm stats (softmax norm fused) ----
    k_bnstats<<<592, 128>>>(N);

    // ---- layer 2 (gemm2 finalizes BN, zeros acc2/den) ----
    size_t smem = (128 * 132 + 64 * 132 + 256) * sizeof(float);  // 102400 B
    cudaFuncSetAttribute(k_gemm2, cudaFuncAttributeMaxDynamicSharedMemorySize, (int)smem);
    dim3 g2((N + 127) / 128, 5);
    k_gemm2<<<g2, 256, smem>>>(nt, w2, wres2, b2, asrc2, adst2, gamma, beta, N);
    k_edge2A<<<(E * 4 + 255) / 256, 256>>>(src, dstp, E);
    k_aggr2<<<(E + 7) / 8, 256>>>(src, dstp, E);

    // ---- epilogue ----
    k_final<<<(N * 32 + 255) / 256, 256>>>((float4*)d_out, N);
}

// round 10
// speedup vs baseline: 1.0352x; 1.0352x over previous
#include <cuda_runtime.h>
#include <cuda_fp16.h>
#include <math.h>
#include <stdint.h>

// ---------------- problem-size bounds (N=50000, E=400000 in dataset) ----------
#define MAXN 50176
#define MAXE 400384

// ---------------- device scratch (no mallocs allowed) -------------------------
__device__ __half  g_h1h[MAXN * 128];            // layer1 node embeddings (fp16)
__device__ float  g_res [MAXN * 128];            // residual (res1 then res2)
__device__ float  g_acc1[MAXN * 128];            // layer1 aggregate -> y -> BN input
__device__ __half  g_h2h[(size_t)MAXN * 512];    // layer2 node embeddings (fp16)
__device__ float  g_acc2[MAXN * 128];            // layer2 head-averaged aggregate
__device__ float  g_s[MAXN * 4], g_d[MAXN * 4];  // attention src/dst terms
__device__ float  g_den[MAXN * 4];
__device__ float  g_alpha[MAXE * 4];             // layer2 ex values
__device__ float  g_e2[MAXE * 4];                // layer2 edge attention term
__device__ double g_colsum[128], g_colsq[128];
__device__ float  g_aew1T[4 * 64], g_aew2T[4 * 64];  // transposed [h][k]
__device__ float  g_eea1[4 * 4],  g_eea2[4 * 4];
__device__ float  g_ne1w1[3 * 128], g_ne2w2[3 * 512];

// ---------------- helpers ------------------------------------------------------
__device__ __forceinline__ void red4(float* p, float a, float b, float c, float d) {
    asm volatile("red.global.add.v4.f32 [%0], {%1,%2,%3,%4};"
                 :: "l"(p), "f"(a), "f"(b), "f"(c), "f"(d) : "memory");
}

// Packed fp32x2 FMA (sm_100+): acc.lo += a.lo*b.lo; acc.hi += a.hi*b.hi (exact fp32)
__device__ __forceinline__ void ffma2(uint64_t& acc, uint64_t a, uint64_t b) {
    asm volatile("fma.rn.f32x2 %0, %1, %2, %0;" : "+l"(acc) : "l"(a), "l"(b));
}
__device__ __forceinline__ uint64_t pack2(float x, float y) {
    uint64_t r; asm("mov.b64 %0, {%1, %2};" : "=l"(r) : "f"(x), "f"(y)); return r;
}
__device__ __forceinline__ float2 unpack2(uint64_t v) {
    float2 r; asm("mov.b64 {%0, %1}, %2;" : "=f"(r.x), "=f"(r.y) : "l"(v)); return r;
}

// ---------------- precompute: fold linear maps (+ zero colsum) ------------------
__global__ void k_pre_a(const float* __restrict__ we1, const float* __restrict__ aedge1,
                        const float* __restrict__ we2, const float* __restrict__ aedge2,
                        const float* __restrict__ ne1, const float* __restrict__ w1,
                        const float* __restrict__ ne2, const float* __restrict__ w2) {
    int i = blockIdx.x * blockDim.x + threadIdx.x;
    if (i < 128) { g_colsum[i] = 0.0; g_colsq[i] = 0.0; }
    if (i < 256) {                       // aeW1^T: [4][64], C=32
        int k = i >> 2, h = i & 3; float a = 0.f;
        for (int c = 0; c < 32; c++) a += we1[k * 128 + h * 32 + c] * aedge1[h * 32 + c];
        g_aew1T[h * 64 + k] = a;
    } else if (i < 512) {                // aeW2^T: [4][64], C=128
        int j = i - 256; int k = j >> 2, h = j & 3; float a = 0.f;
        for (int c = 0; c < 128; c++) a += we2[k * 512 + h * 128 + c] * aedge2[h * 128 + c];
        g_aew2T[h * 64 + k] = a;
    } else if (i < 896) {                // ne1@w1: [3,128]
        int j = i - 512; int t = j >> 7, col = j & 127; float a = 0.f;
        for (int k = 0; k < 32; k++) a += ne1[t * 32 + k] * w1[k * 128 + col];
        g_ne1w1[j] = a;
    } else if (i < 2432) {               // ne2@w2: [3,512]
        int j = i - 896; int t = j >> 9, col = j & 511; float a = 0.f;
        for (int k = 0; k < 128; k++) a += ne2[t * 128 + k] * w2[k * 512 + col];
        g_ne2w2[j] = a;
    }
}

__global__ void k_pre_b(const float* __restrict__ ee1, const float* __restrict__ ee2) {
    int i = threadIdx.x;
    if (i < 16) {
        int t = i >> 2, h = i & 3; float a = 0.f;
        for (int k = 0; k < 64; k++) a += ee1[t * 64 + k] * g_aew1T[h * 64 + k];
        g_eea1[i] = a;
    } else if (i < 32) {
        int j = i - 16; int t = j >> 2, h = j & 3; float a = 0.f;
        for (int k = 0; k < 64; k++) a += ee2[t * 64 + k] * g_aew2T[h * 64 + k];
        g_eea2[j] = a;
    }
}

// ---------------- layer 1 GEMM: 128-row tile, ct on blockIdx.y, fused sd1/zeroing -
__global__ void __launch_bounds__(256, 2)
k_gemm1(const float* __restrict__ x, const int* __restrict__ nt,
        const float* __restrict__ w1, const float* __restrict__ wres1,
        const float* __restrict__ b1,
        const float* __restrict__ asrc, const float* __restrict__ adst, int N) {
    __shared__ __align__(16) float sXT[32][132];   // [k][r]
    __shared__ __align__(16) float sW[32][132];    // [k][c]
    __shared__ float sA[128], sD[128];
    int t = threadIdx.x;           // 256
    int r0 = blockIdx.x * 128;
    int ct = blockIdx.y;           // 0: w1 + sd dots, 1: wres1 + acc zeroing
    int tc = t & 15, tr = t >> 4;

    for (int i = t; i < 128 * 32; i += 256) {
        int r = i >> 5, k = i & 31;
        int gr = r0 + r;
        sXT[k][r] = (gr < N) ? x[(size_t)gr * 32 + k] : 0.f;
    }
    if (ct == 0 && t < 128) { sA[t] = asrc[t]; sD[t] = adst[t]; }
    {
        const float* wp = ct ? wres1 : w1;
        for (int i = t; i < 32 * 32; i += 256) {
            int k = i >> 5, c4 = i & 31;
            *reinterpret_cast<float4*>(&sW[k][c4 * 4]) =
                *reinterpret_cast<const float4*>(&wp[k * 128 + c4 * 4]);
        }
    }
    __syncthreads();

    uint64_t acc[8][4];
    #pragma unroll
    for (int j = 0; j < 8; j++)
        #pragma unroll
        for (int p = 0; p < 4; p++) acc[j][p] = 0ull;

    #pragma unroll 8
    for (int k = 0; k < 32; k++) {
        float4 xa = *reinterpret_cast<const float4*>(&sXT[k][tr * 8]);
        float4 xb = *reinterpret_cast<const float4*>(&sXT[k][tr * 8 + 4]);
        ulonglong2 wa = *reinterpret_cast<const ulonglong2*>(&sW[k][tc * 8]);
        ulonglong2 wb = *reinterpret_cast<const ulonglong2*>(&sW[k][tc * 8 + 4]);
        float xs[8] = {xa.x, xa.y, xa.z, xa.w, xb.x, xb.y, xb.z, xb.w};
        #pragma unroll
        for (int j = 0; j < 8; j++) {
            uint64_t x2 = pack2(xs[j], xs[j]);
            ffma2(acc[j][0], x2, wa.x);
            ffma2(acc[j][1], x2, wa.y);
            ffma2(acc[j][2], x2, wb.x);
            ffma2(acc[j][3], x2, wb.y);
        }
    }

    if (ct == 0) {
        float av[8], dv[8];
        #pragma unroll
        for (int i = 0; i < 8; i++) { av[i] = sA[tc * 8 + i]; dv[i] = sD[tc * 8 + i]; }
        int head = tc >> 2;
        #pragma unroll
        for (int j = 0; j < 8; j++) {
            int gr = r0 + tr * 8 + j;
            float o[8];
            #pragma unroll
            for (int p = 0; p < 4; p++) {
                float2 u = unpack2(acc[j][p]);
                o[2 * p] = u.x; o[2 * p + 1] = u.y;
            }
            int ty = (gr < N) ? nt[gr] : 0;
            const float* bias = &g_ne1w1[ty * 128 + tc * 8];
            float sp = 0.f, dp = 0.f;
            #pragma unroll
            for (int i = 0; i < 8; i++) {
                o[i] += bias[i];
                sp += o[i] * av[i];
                dp += o[i] * dv[i];
            }
            sp += __shfl_xor_sync(0xffffffffu, sp, 1);
            sp += __shfl_xor_sync(0xffffffffu, sp, 2);
            dp += __shfl_xor_sync(0xffffffffu, dp, 1);
            dp += __shfl_xor_sync(0xffffffffu, dp, 2);
            if (gr < N) {
                __half2 hh[4];
                #pragma unroll
                for (int p = 0; p < 4; p++) hh[p] = __floats2half2_rn(o[2 * p], o[2 * p + 1]);
                *reinterpret_cast<uint4*>(&g_h1h[(size_t)gr * 128 + tc * 8]) =
                    *reinterpret_cast<uint4*>(hh);
                if ((tc & 3) == 0) {
                    g_s[gr * 4 + head] = sp; g_d[gr * 4 + head] = dp;
                    g_den[gr * 4 + head] = 0.f;
                }
            }
        }
    } else {
        float bb[8];
        #pragma unroll
        for (int i = 0; i < 8; i++) bb[i] = b1[tc * 8 + i];
        float4 z4 = make_float4(0.f, 0.f, 0.f, 0.f);
        #pragma unroll
        for (int j = 0; j < 8; j++) {
            int gr = r0 + tr * 8 + j; if (gr >= N) continue;
            float o[8];
            #pragma unroll
            for (int p = 0; p < 4; p++) {
                float2 u = unpack2(acc[j][p]);
                o[2 * p] = u.x; o[2 * p + 1] = u.y;
            }
            float* dst = &g_res[(size_t)gr * 128 + tc * 8];
            *reinterpret_cast<float4*>(dst) =
                make_float4(o[0] + bb[0], o[1] + bb[1], o[2] + bb[2], o[3] + bb[3]);
            *reinterpret_cast<float4*>(dst + 4) =
                make_float4(o[4] + bb[4], o[5] + bb[5], o[6] + bb[6], o[7] + bb[7]);
            float* az = &g_acc1[(size_t)gr * 128 + tc * 8];
            *reinterpret_cast<float4*>(az)     = z4;
            *reinterpret_cast<float4*>(az + 4) = z4;
        }
    }
}

// ---------------- layer 1 fused edge phase (round-8 struct, fp16 gather) ----------
__global__ void __launch_bounds__(256)
k_edge1(const int* __restrict__ src, const int* __restrict__ dst,
        const float* __restrict__ ea, const int* __restrict__ et, int E) {
    __shared__ __align__(16) float sa1[4][64], sa2[4][64];
    __shared__ float se1[16], se2[16];
    int t = threadIdx.x;  // 256
    sa1[t >> 6][t & 63] = g_aew1T[t];
    sa2[t >> 6][t & 63] = g_aew2T[t];
    if (t < 16) { se1[t] = g_eea1[t]; se2[t] = g_eea2[t]; }
    __syncthreads();
    int l = t & 31, li = l & 7;
    int e = blockIdx.x * 32 + (t >> 5) * 4 + (l >> 3);
    bool valid = e < E;
    float e1[4] = {0, 0, 0, 0}, e2[4] = {0, 0, 0, 0};
    int s_ = 0, d_ = 0;
    if (valid) {
        s_ = src[e]; d_ = dst[e];
        const float* row = ea + (size_t)e * 64 + li * 8;
        float4 va = *reinterpret_cast<const float4*>(row);
        float4 vb = *reinterpret_cast<const float4*>(row + 4);
        float vs[8] = {va.x, va.y, va.z, va.w, vb.x, vb.y, vb.z, vb.w};
        #pragma unroll
        for (int h = 0; h < 4; h++) {
            float4 w0 = *reinterpret_cast<const float4*>(&sa1[h][li * 8]);
            float4 w1v = *reinterpret_cast<const float4*>(&sa1[h][li * 8 + 4]);
            float4 u0 = *reinterpret_cast<const float4*>(&sa2[h][li * 8]);
            float4 u1 = *reinterpret_cast<const float4*>(&sa2[h][li * 8 + 4]);
            e1[h] = vs[0]*w0.x + vs[1]*w0.y + vs[2]*w0.z + vs[3]*w0.w
                  + vs[4]*w1v.x + vs[5]*w1v.y + vs[6]*w1v.z + vs[7]*w1v.w;
            e2[h] = vs[0]*u0.x + vs[1]*u0.y + vs[2]*u0.z + vs[3]*u0.w
                  + vs[4]*u1.x + vs[5]*u1.y + vs[6]*u1.z + vs[7]*u1.w;
        }
    }
    #pragma unroll
    for (int h = 0; h < 4; h++)
        #pragma unroll
        for (int o = 1; o < 8; o <<= 1) {
            e1[h] += __shfl_xor_sync(0xffffffffu, e1[h], o);
            e2[h] += __shfl_xor_sync(0xffffffffu, e2[h], o);
        }
    float ex = 0.f;
    if (valid && li < 4) {
        float ev1 = (li == 0) ? e1[0] : (li == 1) ? e1[1] : (li == 2) ? e1[2] : e1[3];
        float ev2 = (li == 0) ? e2[0] : (li == 1) ? e2[1] : (li == 2) ? e2[2] : e2[3];
        int ty = et[e];
        float a = g_s[s_ * 4 + li] + g_d[d_ * 4 + li] + ev1 + se1[ty * 4 + li];
        a = (a >= 0.f) ? a : 0.2f * a;
        ex = __expf(a);
        atomicAdd(&g_den[d_ * 4 + li], ex);
        g_e2[e * 4 + li] = ev2 + se2[ty * 4 + li];
    }
    float exh = __shfl_sync(0xffffffffu, ex, (l & 24) + (li >> 1));
    if (valid) {
        // gather 16 halves (32B) for columns [li*16, li*16+16)
        const uint4* hb = reinterpret_cast<const uint4*>(&g_h1h[(size_t)s_ * 128 + li * 16]);
        float* ab = &g_acc1[(size_t)d_ * 128 + li * 16];
        #pragma unroll
        for (int q = 0; q < 2; q++) {
            uint4 pk = hb[q];
            __half2* hp = reinterpret_cast<__half2*>(&pk);
            float2 f0 = __half22float2(hp[0]);
            float2 f1 = __half22float2(hp[1]);
            float2 f2 = __half22float2(hp[2]);
            float2 f3 = __half22float2(hp[3]);
            red4(ab + q * 8,     f0.x * exh, f0.y * exh, f1.x * exh, f1.y * exh);
            red4(ab + q * 8 + 4, f2.x * exh, f2.y * exh, f3.x * exh, f3.y * exh);
        }
    }
}

// ---------------- BN stats: y = acc1/den + res (softmax norm fused) --------------
__global__ void k_bnstats(int N) {
    int t = threadIdx.x;  // 128
    int hh = t >> 5;
    double s = 0.0, q = 0.0;
    for (int n = blockIdx.x; n < N; n += gridDim.x) {
        float den = g_den[n * 4 + hh] + 1e-16f;
        float y = g_acc1[(size_t)n * 128 + t] / den + g_res[(size_t)n * 128 + t];
        g_acc1[(size_t)n * 128 + t] = y;
        s += y; q += (double)y * y;
    }
    atomicAdd(&g_colsum[t], s);
    atomicAdd(&g_colsq[t], q);
}

// ---------------- layer 2 GEMM: ct on blockIdx.y, fused BN-finalize/sd2/zeroing ---
__global__ void __launch_bounds__(256, 2)
k_gemm2(const int* __restrict__ nt, const float* __restrict__ w2,
        const float* __restrict__ wres2, const float* __restrict__ b2,
        const float* __restrict__ asrc, const float* __restrict__ adst,
        const float* __restrict__ gamma, const float* __restrict__ beta, int N) {
    extern __shared__ __align__(16) float sm[];
    float* sXT = sm;               // [k:128][r:132 pad]  (BN applied)
    float* sW  = sm + 128 * 132;   // [k:64][c:132 pad]
    float* sScale = sm + 128 * 132 + 64 * 132;
    float* sShift = sScale + 128;
    int t = threadIdx.x;           // 256
    int r0 = blockIdx.x * 128;
    int ct = blockIdx.y;           // 0..3: w2 col-tiles (+sd dots), 4: wres2 (+zeroing)
    int tc = t & 15, tr = t >> 4;

    if (t < 128) {                 // BN finalize (per block, cheap)
        double mu = g_colsum[t] / N;
        double var = g_colsq[t] / N - mu * mu;
        double sc = (double)gamma[t] / sqrt(var + 1e-5);
        sScale[t] = (float)sc;
        sShift[t] = (float)((double)beta[t] - mu * sc);
    }
    __syncthreads();

    for (int i = t; i < 128 * 128; i += 256) {
        int r = i >> 7, k = i & 127; int gr = r0 + r;
        float v = 0.f;
        if (gr < N) v = g_acc1[(size_t)gr * 128 + k] * sScale[k] + sShift[k];
        sXT[k * 132 + r] = v;
    }

    uint64_t acc[8][4];
    #pragma unroll
    for (int j = 0; j < 8; j++)
        #pragma unroll
        for (int p = 0; p < 4; p++) acc[j][p] = 0ull;

    for (int kh = 0; kh < 2; kh++) {
        __syncthreads();
        for (int i = t; i < 64 * 32; i += 256) {
            int k = i >> 5, c4 = i & 31;
            float4 wv;
            if (ct < 4) wv = *reinterpret_cast<const float4*>(
                             &w2[(size_t)(kh * 64 + k) * 512 + ct * 128 + c4 * 4]);
            else        wv = *reinterpret_cast<const float4*>(
                             &wres2[(size_t)(kh * 64 + k) * 128 + c4 * 4]);
            *reinterpret_cast<float4*>(&sW[k * 132 + c4 * 4]) = wv;
        }
        __syncthreads();

        const float* xbase = sXT + kh * 64 * 132 + tr * 8;
        const float* wbase = sW + tc * 8;
        #pragma unroll 4
        for (int k = 0; k < 64; k++) {
            float4 xa = *reinterpret_cast<const float4*>(xbase + k * 132);
            float4 xb = *reinterpret_cast<const float4*>(xbase + k * 132 + 4);
            ulonglong2 wa = *reinterpret_cast<const ulonglong2*>(wbase + k * 132);
            ulonglong2 wb = *reinterpret_cast<const ulonglong2*>(wbase + k * 132 + 4);
            float xs[8] = {xa.x, xa.y, xa.z, xa.w, xb.x, xb.y, xb.z, xb.w};
            #pragma unroll
            for (int j = 0; j < 8; j++) {
                uint64_t x2 = pack2(xs[j], xs[j]);
                ffma2(acc[j][0], x2, wa.x);
                ffma2(acc[j][1], x2, wa.y);
                ffma2(acc[j][2], x2, wb.x);
                ffma2(acc[j][3], x2, wb.y);
            }
        }
    }

    if (ct < 4) {
        float av[8], dv[8];
        #pragma unroll
        for (int i = 0; i < 8; i++) {
            av[i] = asrc[ct * 128 + tc * 8 + i];
            dv[i] = adst[ct * 128 + tc * 8 + i];
        }
        #pragma unroll
        for (int j = 0; j < 8; j++) {
            int gr = r0 + tr * 8 + j;
            float o[8];
            #pragma unroll
            for (int p = 0; p < 4; p++) {
                float2 u = unpack2(acc[j][p]);
                o[2 * p] = u.x; o[2 * p + 1] = u.y;
            }
            int ty = (gr < N) ? nt[gr] : 0;
            const float* bias = &g_ne2w2[ty * 512 + ct * 128 + tc * 8];
            float sp = 0.f, dp = 0.f;
            #pragma unroll
            for (int i = 0; i < 8; i++) {
                o[i] += bias[i];
                sp += o[i] * av[i];
                dp += o[i] * dv[i];
            }
            #pragma unroll
            for (int off = 8; off; off >>= 1) {
                sp += __shfl_xor_sync(0xffffffffu, sp, off);
                dp += __shfl_xor_sync(0xffffffffu, dp, off);
            }
            if (gr < N) {
                __half2 hh[4];
                #pragma unroll
                for (int p = 0; p < 4; p++) hh[p] = __floats2half2_rn(o[2 * p], o[2 * p + 1]);
                *reinterpret_cast<uint4*>(&g_h2h[(size_t)gr * 512 + ct * 128 + tc * 8]) =
                    *reinterpret_cast<uint4*>(hh);
                if (tc == 0) {
                    g_s[gr * 4 + ct] = sp; g_d[gr * 4 + ct] = dp;
                    g_den[gr * 4 + ct] = 0.f;
                }
            }
        }
    } else {
        float4 z4 = make_float4(0.f, 0.f, 0.f, 0.f);
        #pragma unroll
        for (int j = 0; j < 8; j++) {
            int gr = r0 + tr * 8 + j; if (gr >= N) continue;
            float o[8];
            #pragma unroll
            for (int p = 0; p < 4; p++) {
                float2 u = unpack2(acc[j][p]);
                o[2 * p] = u.x; o[2 * p + 1] = u.y;
            }
            const float* bias = &b2[tc * 8];
            float* dst = &g_res[(size_t)gr * 128 + tc * 8];
            *reinterpret_cast<float4*>(dst) =
                make_float4(o[0] + bias[0], o[1] + bias[1], o[2] + bias[2], o[3] + bias[3]);
            *reinterpret_cast<float4*>(dst + 4) =
                make_float4(o[4] + bias[4], o[5] + bias[5], o[6] + bias[6], o[7] + bias[7]);
            float* az = &g_acc2[(size_t)gr * 128 + tc * 8];
            *reinterpret_cast<float4*>(az)     = z4;
            *reinterpret_cast<float4*>(az + 4) = z4;
        }
    }
}

// ---------------- layer 2 edge pass A: alpha -> ex -> den (no max-sub) ------------
__global__ void k_edge2A(const int* __restrict__ src, const int* __restrict__ dst, int E) {
    int i = blockIdx.x * blockDim.x + threadIdx.x;
    if (i >= E * 4) return;
    int e = i >> 2, h = i & 3;
    int s_ = src[e], d_ = dst[e];
    float a = g_s[s_ * 4 + h] + g_d[d_ * 4 + h] + g_e2[i];
    a = (a >= 0.f) ? a : 0.2f * a;
    float ex = __expf(a);
    g_alpha[i] = ex;
    atomicAdd(&g_den[d_ * 4 + h], ex);
}

// ---------------- edge aggregate layer 2 (head-mean fused, fp16 gather) -----------
// Lanes 0-15 combine heads 0/1 for col-block m=l&15; lanes 16-31 heads 2/3;
// partner sums merged via shfl_xor 16, lanes 0-15 issue the red4.
__global__ void k_aggr2(const int* __restrict__ src, const int* __restrict__ dst, int E) {
    int e = blockIdx.x * 8 + (threadIdx.x >> 5); if (e >= E) return;
    int l = threadIdx.x & 31;
    int s_ = src[e], d_ = dst[e];
    float cf = 0.f;
    if (l < 4) cf = 0.25f * g_alpha[e * 4 + l] / (g_den[d_ * 4 + l] + 1e-16f);
    int m = l & 15, hp = l >> 4;          // head pair: 0 -> heads 0,1 ; 1 -> heads 2,3
    float ca = __shfl_sync(0xffffffffu, cf, 2 * hp);
    float cb = __shfl_sync(0xffffffffu, cf, 2 * hp + 1);
    const uint4* hs = reinterpret_cast<const uint4*>(&g_h2h[(size_t)s_ * 512]);
    uint4 qa = hs[hp * 32 + m];           // head 2*hp,   cols m*8..m*8+7
    uint4 qb = hs[hp * 32 + 16 + m];      // head 2*hp+1, same cols
    __half2* pa = reinterpret_cast<__half2*>(&qa);
    __half2* pb = reinterpret_cast<__half2*>(&qb);
    float r[8];
    #pragma unroll
    for (int i = 0; i < 4; i++) {
        float2 fa = __half22float2(pa[i]);
        float2 fb = __half22float2(pb[i]);
        r[2 * i]     = ca * fa.x + cb * fb.x;
        r[2 * i + 1] = ca * fa.y + cb * fb.y;
    }
    #pragma unroll
    for (int i = 0; i < 8; i++) r[i] += __shfl_xor_sync(0xffffffffu, r[i], 16);
    if (l < 16) {
        float* ab = &g_acc2[(size_t)d_ * 128 + m * 8];
        red4(ab,     r[0], r[1], r[2], r[3]);
        red4(ab + 4, r[4], r[5], r[6], r[7]);
    }
}

// ---------------- final: out = acc2 + res2 -----------------------------------------
__global__ void k_final(float4* __restrict__ out, int N) {
    int i = blockIdx.x * blockDim.x + threadIdx.x;
    if (i >= N * 32) return;
    const float4 a = reinterpret_cast<const float4*>(g_acc2)[i];
    const float4 r = reinterpret_cast<const float4*>(g_res)[i];
    out[i] = make_float4(a.x + r.x, a.y + r.y, a.z + r.z, a.w + r.w);
}

// ---------------- host launch ----------------------------------------------------
extern "C" void kernel_launch(void* const* d_in, const int* in_sizes, int n_in,
                              void* d_out, int out_size) {
    const float* x      = (const float*)d_in[0];
    const int*   ei     = (const int*)  d_in[1];
    const int*   nt     = (const int*)  d_in[2];
    const float* ea     = (const float*)d_in[3];
    const int*   et     = (const int*)  d_in[4];
    const float* ne1    = (const float*)d_in[5];
    const float* w1     = (const float*)d_in[6];
    const float* we1    = (const float*)d_in[7];
    const float* asrc1  = (const float*)d_in[8];
    const float* adst1  = (const float*)d_in[9];
    const float* aedge1 = (const float*)d_in[10];
    const float* ee1    = (const float*)d_in[11];
    const float* wres1  = (const float*)d_in[12];
    const float* b1     = (const float*)d_in[13];
    const float* gamma  = (const float*)d_in[14];
    const float* beta   = (const float*)d_in[15];
    const float* ne2    = (const float*)d_in[16];
    const float* w2     = (const float*)d_in[17];
    const float* we2    = (const float*)d_in[18];
    const float* asrc2  = (const float*)d_in[19];
    const float* adst2  = (const float*)d_in[20];
    const float* aedge2 = (const float*)d_in[21];
    const float* ee2    = (const float*)d_in[22];
    const float* wres2  = (const float*)d_in[23];
    const float* b2     = (const float*)d_in[24];

    int N = in_sizes[0] / 32;
    int E = in_sizes[4];
    const int* src = ei;
    const int* dstp = ei + E;

    // ---- precompute (also zeros colsum/colsq) ----
    k_pre_a<<<10, 256>>>(we1, aedge1, we2, aedge2, ne1, w1, ne2, w2);
    k_pre_b<<<1, 32>>>(ee1, ee2);

    // ---- layer 1 (gemm1 zeros acc1/den) ----
    dim3 g1((N + 127) / 128, 2);
    k_gemm1<<<g1, 256>>>(x, nt, w1, wres1, b1, asrc1, adst1, N);
    k_edge1<<<(E + 31) / 32, 256>>>(src, dstp, ea, et, E);

    // ---- batch norm stats (softmax norm fused) ----
    k_bnstats<<<592, 128>>>(N);

    // ---- layer 2 (gemm2 finalizes BN, zeros acc2/den) ----
    size_t smem = (128 * 132 + 64 * 132 + 256) * sizeof(float);  // 102400 B
    cudaFuncSetAttribute(k_gemm2, cudaFuncAttributeMaxDynamicSharedMemorySize, (int)smem);
    dim3 g2((N + 127) / 128, 5);
    k_gemm2<<<g2, 256, smem>>>(nt, w2, wres2, b2, asrc2, adst2, gamma, beta, N);
    k_edge2A<<<(E * 4 + 255) / 256, 256>>>(src, dstp, E);
    k_aggr2<<<(E + 7) / 8, 256>>>(src, dstp, E);

    // ---- epilogue ----
    k_final<<<(N * 32 + 255) / 256, 256>>>((float4*)d_out, N);
}

// round 11
// speedup vs baseline: 1.2819x; 1.2384x over previous
#include <cuda_runtime.h>
#include <cuda_fp16.h>
#include <math.h>
#include <stdint.h>

// ---------------- problem-size bounds (N=50000, E=400000 in dataset) ----------
#define MAXN 50176
#define MAXE 400384

// ---------------- device scratch (no mallocs allowed) -------------------------
__device__ __half  g_h1h[MAXN * 128];            // layer1 node embeddings (fp16)
__device__ float  g_res [MAXN * 128];            // residual (res1 then res2)
__device__ float  g_acc1[MAXN * 128];            // layer1 aggregate -> y -> BN input
__device__ __half  g_h2h[(size_t)MAXN * 512];    // layer2 node embeddings (fp16)
__device__ float  g_acc2[MAXN * 128];            // layer2 head-averaged aggregate
__device__ float  g_s[MAXN * 4], g_d[MAXN * 4];  // attention src/dst terms
__device__ float  g_den[MAXN * 4];
__device__ float  g_alpha[MAXE * 4];             // layer2 ex values
__device__ float  g_e2[MAXE * 4];                // layer2 edge attention term
__device__ double g_colsum[128], g_colsq[128];
__device__ float  g_aew1T[4 * 64], g_aew2T[4 * 64];  // transposed [h][k]
__device__ float  g_eea1[4 * 4],  g_eea2[4 * 4];
__device__ float  g_ne1w1[3 * 128], g_ne2w2[3 * 512];
__device__ __half g_w2h[128 * 512];              // fp16 copies of layer2 weights
__device__ __half g_wresh[128 * 128];

// ---------------- helpers ------------------------------------------------------
__device__ __forceinline__ void red4(float* p, float a, float b, float c, float d) {
    asm volatile("red.global.add.v4.f32 [%0], {%1,%2,%3,%4};"
                 :: "l"(p), "f"(a), "f"(b), "f"(c), "f"(d) : "memory");
}

// Packed fp32x2 FMA (sm_100+)
__device__ __forceinline__ void ffma2(uint64_t& acc, uint64_t a, uint64_t b) {
    asm volatile("fma.rn.f32x2 %0, %1, %2, %0;" : "+l"(acc) : "l"(a), "l"(b));
}
__device__ __forceinline__ uint64_t pack2(float x, float y) {
    uint64_t r; asm("mov.b64 %0, {%1, %2};" : "=l"(r) : "f"(x), "f"(y)); return r;
}
__device__ __forceinline__ float2 unpack2(uint64_t v) {
    float2 r; asm("mov.b64 {%0, %1}, %2;" : "=f"(r.x), "=f"(r.y) : "l"(v)); return r;
}
__device__ __forceinline__ uint32_t smem_u32(const void* p) {
    return (uint32_t)__cvta_generic_to_shared(p);
}
__device__ __forceinline__ void ldsm_x4(uint32_t* r, uint32_t addr) {
    asm volatile("ldmatrix.sync.aligned.m8n8.x4.shared.b16 {%0,%1,%2,%3}, [%4];"
                 : "=r"(r[0]), "=r"(r[1]), "=r"(r[2]), "=r"(r[3]) : "r"(addr));
}
__device__ __forceinline__ void ldsm_x2t(uint32_t* r, uint32_t addr) {
    asm volatile("ldmatrix.sync.aligned.m8n8.x2.trans.shared.b16 {%0,%1}, [%2];"
                 : "=r"(r[0]), "=r"(r[1]) : "r"(addr));
}
__device__ __forceinline__ void mma16816(float* d, const uint32_t* a, const uint32_t* b) {
    asm volatile("mma.sync.aligned.m16n8k16.row.col.f32.f16.f16.f32 "
                 "{%0,%1,%2,%3}, {%4,%5,%6,%7}, {%8,%9}, {%0,%1,%2,%3};"
                 : "+f"(d[0]), "+f"(d[1]), "+f"(d[2]), "+f"(d[3])
                 : "r"(a[0]), "r"(a[1]), "r"(a[2]), "r"(a[3]), "r"(b[0]), "r"(b[1]));
}

// ---------------- precompute: fold linear maps (+ zero colsum) ------------------
__global__ void k_pre_a(const float* __restrict__ we1, const float* __restrict__ aedge1,
                        const float* __restrict__ we2, const float* __restrict__ aedge2,
                        const float* __restrict__ ne1, const float* __restrict__ w1,
                        const float* __restrict__ ne2, const float* __restrict__ w2) {
    int i = blockIdx.x * blockDim.x + threadIdx.x;
    if (i < 128) { g_colsum[i] = 0.0; g_colsq[i] = 0.0; }
    if (i < 256) {
        int k = i >> 2, h = i & 3; float a = 0.f;
        for (int c = 0; c < 32; c++) a += we1[k * 128 + h * 32 + c] * aedge1[h * 32 + c];
        g_aew1T[h * 64 + k] = a;
    } else if (i < 512) {
        int j = i - 256; int k = j >> 2, h = j & 3; float a = 0.f;
        for (int c = 0; c < 128; c++) a += we2[k * 512 + h * 128 + c] * aedge2[h * 128 + c];
        g_aew2T[h * 64 + k] = a;
    } else if (i < 896) {
        int j = i - 512; int t = j >> 7, col = j & 127; float a = 0.f;
        for (int k = 0; k < 32; k++) a += ne1[t * 32 + k] * w1[k * 128 + col];
        g_ne1w1[j] = a;
    } else if (i < 2432) {
        int j = i - 896; int t = j >> 9, col = j & 511; float a = 0.f;
        for (int k = 0; k < 128; k++) a += ne2[t * 128 + k] * w2[k * 512 + col];
        g_ne2w2[j] = a;
    }
}

__global__ void k_pre_b(const float* __restrict__ ee1, const float* __restrict__ ee2) {
    int i = threadIdx.x;
    if (i < 16) {
        int t = i >> 2, h = i & 3; float a = 0.f;
        for (int k = 0; k < 64; k++) a += ee1[t * 64 + k] * g_aew1T[h * 64 + k];
        g_eea1[i] = a;
    } else if (i < 32) {
        int j = i - 16; int t = j >> 2, h = j & 3; float a = 0.f;
        for (int k = 0; k < 64; k++) a += ee2[t * 64 + k] * g_aew2T[h * 64 + k];
        g_eea2[j] = a;
    }
}

// fp16 copies of w2 / wres2
__global__ void k_pre_w(const float* __restrict__ w2, const float* __restrict__ wres2) {
    int i = blockIdx.x * blockDim.x + threadIdx.x;
    if (i < 128 * 512) g_w2h[i] = __float2half(w2[i]);
    else if (i < 128 * 512 + 128 * 128) g_wresh[i - 128 * 512] = __float2half(wres2[i - 128 * 512]);
}

// ---------------- layer 1 GEMM (unchanged best: ffma2, ct-split, fused) ----------
__global__ void __launch_bounds__(256, 2)
k_gemm1(const float* __restrict__ x, const int* __restrict__ nt,
        const float* __restrict__ w1, const float* __restrict__ wres1,
        const float* __restrict__ b1,
        const float* __restrict__ asrc, const float* __restrict__ adst, int N) {
    __shared__ __align__(16) float sXT[32][132];
    __shared__ __align__(16) float sW[32][132];
    __shared__ float sA[128], sD[128];
    int t = threadIdx.x;
    int r0 = blockIdx.x * 128;
    int ct = blockIdx.y;
    int tc = t & 15, tr = t >> 4;

    for (int i = t; i < 128 * 32; i += 256) {
        int r = i >> 5, k = i & 31;
        int gr = r0 + r;
        sXT[k][r] = (gr < N) ? x[(size_t)gr * 32 + k] : 0.f;
    }
    if (ct == 0 && t < 128) { sA[t] = asrc[t]; sD[t] = adst[t]; }
    {
        const float* wp = ct ? wres1 : w1;
        for (int i = t; i < 32 * 32; i += 256) {
            int k = i >> 5, c4 = i & 31;
            *reinterpret_cast<float4*>(&sW[k][c4 * 4]) =
                *reinterpret_cast<const float4*>(&wp[k * 128 + c4 * 4]);
        }
    }
    __syncthreads();

    uint64_t acc[8][4];
    #pragma unroll
    for (int j = 0; j < 8; j++)
        #pragma unroll
        for (int p = 0; p < 4; p++) acc[j][p] = 0ull;

    #pragma unroll 8
    for (int k = 0; k < 32; k++) {
        float4 xa = *reinterpret_cast<const float4*>(&sXT[k][tr * 8]);
        float4 xb = *reinterpret_cast<const float4*>(&sXT[k][tr * 8 + 4]);
        ulonglong2 wa = *reinterpret_cast<const ulonglong2*>(&sW[k][tc * 8]);
        ulonglong2 wb = *reinterpret_cast<const ulonglong2*>(&sW[k][tc * 8 + 4]);
        float xs[8] = {xa.x, xa.y, xa.z, xa.w, xb.x, xb.y, xb.z, xb.w};
        #pragma unroll
        for (int j = 0; j < 8; j++) {
            uint64_t x2 = pack2(xs[j], xs[j]);
            ffma2(acc[j][0], x2, wa.x);
            ffma2(acc[j][1], x2, wa.y);
            ffma2(acc[j][2], x2, wb.x);
            ffma2(acc[j][3], x2, wb.y);
        }
    }

    if (ct == 0) {
        float av[8], dv[8];
        #pragma unroll
        for (int i = 0; i < 8; i++) { av[i] = sA[tc * 8 + i]; dv[i] = sD[tc * 8 + i]; }
        int head = tc >> 2;
        #pragma unroll
        for (int j = 0; j < 8; j++) {
            int gr = r0 + tr * 8 + j;
            float o[8];
            #pragma unroll
            for (int p = 0; p < 4; p++) {
                float2 u = unpack2(acc[j][p]);
                o[2 * p] = u.x; o[2 * p + 1] = u.y;
            }
            int ty = (gr < N) ? nt[gr] : 0;
            const float* bias = &g_ne1w1[ty * 128 + tc * 8];
            float sp = 0.f, dp = 0.f;
            #pragma unroll
            for (int i = 0; i < 8; i++) {
                o[i] += bias[i];
                sp += o[i] * av[i];
                dp += o[i] * dv[i];
            }
            sp += __shfl_xor_sync(0xffffffffu, sp, 1);
            sp += __shfl_xor_sync(0xffffffffu, sp, 2);
            dp += __shfl_xor_sync(0xffffffffu, dp, 1);
            dp += __shfl_xor_sync(0xffffffffu, dp, 2);
            if (gr < N) {
                __half2 hh[4];
                #pragma unroll
                for (int p = 0; p < 4; p++) hh[p] = __floats2half2_rn(o[2 * p], o[2 * p + 1]);
                *reinterpret_cast<uint4*>(&g_h1h[(size_t)gr * 128 + tc * 8]) =
                    *reinterpret_cast<uint4*>(hh);
                if ((tc & 3) == 0) {
                    g_s[gr * 4 + head] = sp; g_d[gr * 4 + head] = dp;
                    g_den[gr * 4 + head] = 0.f;
                }
            }
        }
    } else {
        float bb[8];
        #pragma unroll
        for (int i = 0; i < 8; i++) bb[i] = b1[tc * 8 + i];
        float4 z4 = make_float4(0.f, 0.f, 0.f, 0.f);
        #pragma unroll
        for (int j = 0; j < 8; j++) {
            int gr = r0 + tr * 8 + j; if (gr >= N) continue;
            float o[8];
            #pragma unroll
            for (int p = 0; p < 4; p++) {
                float2 u = unpack2(acc[j][p]);
                o[2 * p] = u.x; o[2 * p + 1] = u.y;
            }
            float* dst = &g_res[(size_t)gr * 128 + tc * 8];
            *reinterpret_cast<float4*>(dst) =
                make_float4(o[0] + bb[0], o[1] + bb[1], o[2] + bb[2], o[3] + bb[3]);
            *reinterpret_cast<float4*>(dst + 4) =
                make_float4(o[4] + bb[4], o[5] + bb[5], o[6] + bb[6], o[7] + bb[7]);
            float* az = &g_acc1[(size_t)gr * 128 + tc * 8];
            *reinterpret_cast<float4*>(az)     = z4;
            *reinterpret_cast<float4*>(az + 4) = z4;
        }
    }
}

// ---------------- layer 1 fused edge phase (unchanged best) -----------------------
__global__ void __launch_bounds__(256)
k_edge1(const int* __restrict__ src, const int* __restrict__ dst,
        const float* __restrict__ ea, const int* __restrict__ et, int E) {
    __shared__ __align__(16) float sa1[4][64], sa2[4][64];
    __shared__ float se1[16], se2[16];
    int t = threadIdx.x;
    sa1[t >> 6][t & 63] = g_aew1T[t];
    sa2[t >> 6][t & 63] = g_aew2T[t];
    if (t < 16) { se1[t] = g_eea1[t]; se2[t] = g_eea2[t]; }
    __syncthreads();
    int l = t & 31, li = l & 7;
    int e = blockIdx.x * 32 + (t >> 5) * 4 + (l >> 3);
    bool valid = e < E;
    float e1[4] = {0, 0, 0, 0}, e2[4] = {0, 0, 0, 0};
    int s_ = 0, d_ = 0;
    if (valid) {
        s_ = src[e]; d_ = dst[e];
        const float* row = ea + (size_t)e * 64 + li * 8;
        float4 va = *reinterpret_cast<const float4*>(row);
        float4 vb = *reinterpret_cast<const float4*>(row + 4);
        float vs[8] = {va.x, va.y, va.z, va.w, vb.x, vb.y, vb.z, vb.w};
        #pragma unroll
        for (int h = 0; h < 4; h++) {
            float4 w0 = *reinterpret_cast<const float4*>(&sa1[h][li * 8]);
            float4 w1v = *reinterpret_cast<const float4*>(&sa1[h][li * 8 + 4]);
            float4 u0 = *reinterpret_cast<const float4*>(&sa2[h][li * 8]);
            float4 u1 = *reinterpret_cast<const float4*>(&sa2[h][li * 8 + 4]);
            e1[h] = vs[0]*w0.x + vs[1]*w0.y + vs[2]*w0.z + vs[3]*w0.w
                  + vs[4]*w1v.x + vs[5]*w1v.y + vs[6]*w1v.z + vs[7]*w1v.w;
            e2[h] = vs[0]*u0.x + vs[1]*u0.y + vs[2]*u0.z + vs[3]*u0.w
                  + vs[4]*u1.x + vs[5]*u1.y + vs[6]*u1.z + vs[7]*u1.w;
        }
    }
    #pragma unroll
    for (int h = 0; h < 4; h++)
        #pragma unroll
        for (int o = 1; o < 8; o <<= 1) {
            e1[h] += __shfl_xor_sync(0xffffffffu, e1[h], o);
            e2[h] += __shfl_xor_sync(0xffffffffu, e2[h], o);
        }
    float ex = 0.f;
    if (valid && li < 4) {
        float ev1 = (li == 0) ? e1[0] : (li == 1) ? e1[1] : (li == 2) ? e1[2] : e1[3];
        float ev2 = (li == 0) ? e2[0] : (li == 1) ? e2[1] : (li == 2) ? e2[2] : e2[3];
        int ty = et[e];
        float a = g_s[s_ * 4 + li] + g_d[d_ * 4 + li] + ev1 + se1[ty * 4 + li];
        a = (a >= 0.f) ? a : 0.2f * a;
        ex = __expf(a);
        atomicAdd(&g_den[d_ * 4 + li], ex);
        g_e2[e * 4 + li] = ev2 + se2[ty * 4 + li];
    }
    float exh = __shfl_sync(0xffffffffu, ex, (l & 24) + (li >> 1));
    if (valid) {
        const uint4* hb = reinterpret_cast<const uint4*>(&g_h1h[(size_t)s_ * 128 + li * 16]);
        float* ab = &g_acc1[(size_t)d_ * 128 + li * 16];
        #pragma unroll
        for (int q = 0; q < 2; q++) {
            uint4 pk = hb[q];
            __half2* hp = reinterpret_cast<__half2*>(&pk);
            float2 f0 = __half22float2(hp[0]);
            float2 f1 = __half22float2(hp[1]);
            float2 f2 = __half22float2(hp[2]);
            float2 f3 = __half22float2(hp[3]);
            red4(ab + q * 8,     f0.x * exh, f0.y * exh, f1.x * exh, f1.y * exh);
            red4(ab + q * 8 + 4, f2.x * exh, f2.y * exh, f3.x * exh, f3.y * exh);
        }
    }
}

// ---------------- BN stats (unchanged) --------------------------------------------
__global__ void k_bnstats(int N) {
    int t = threadIdx.x;
    int hh = t >> 5;
    double s = 0.0, q = 0.0;
    for (int n = blockIdx.x; n < N; n += gridDim.x) {
        float den = g_den[n * 4 + hh] + 1e-16f;
        float y = g_acc1[(size_t)n * 128 + t] / den + g_res[(size_t)n * 128 + t];
        g_acc1[(size_t)n * 128 + t] = y;
        s += y; q += (double)y * y;
    }
    atomicAdd(&g_colsum[t], s);
    atomicAdd(&g_colsq[t], q);
}

// ---------------- layer 2 GEMM v3: fp16 tensor-core (m16n8k16), single-stage ------
// smem: XH half[128][136] @0 (34816B) | WH half[128][136] @34816 (34816B)
//       D fp32[128][130] overlays @0 after mainloop | sScale@69632 sShift@70144
__global__ void __launch_bounds__(256, 2)
k_gemm2(const int* __restrict__ nt, const float* __restrict__ b2,
        const float* __restrict__ asrc, const float* __restrict__ adst,
        const float* __restrict__ gamma, const float* __restrict__ beta, int N) {
    extern __shared__ __align__(16) char smraw[];
    __half* XH = reinterpret_cast<__half*>(smraw);                  // [128][136]
    __half* WH = reinterpret_cast<__half*>(smraw + 34816);          // [128][136]
    float*  Dsm = reinterpret_cast<float*>(smraw);                  // [128][130] (after)
    float*  sScale = reinterpret_cast<float*>(smraw + 69632);
    float*  sShift = reinterpret_cast<float*>(smraw + 70144);
    int t = threadIdx.x;           // 256
    int r0 = blockIdx.x * 128;
    int ct = blockIdx.y;           // 0..3: w2 col-tiles (+sd dots), 4: wres2 (+zeroing)
    int lane = t & 31, w = t >> 5;
    int warpM = w >> 2, warpN = w & 3;   // 2 x 4 warp grid

    if (t < 128) {
        double mu = g_colsum[t] / N;
        double var = g_colsq[t] / N - mu * mu;
        double sc = (double)gamma[t] / sqrt(var + 1e-5);
        sScale[t] = (float)sc;
        sShift[t] = (float)((double)beta[t] - mu * sc);
    }
    __syncthreads();

    // stage X (BN applied, fp16): [r][k]
    for (int i = t; i < 2048; i += 256) {
        int r = i >> 4, kc = (i & 15) * 8;
        int gr = r0 + r;
        __half2 hh[4];
        if (gr < N) {
            float4 xa = *reinterpret_cast<const float4*>(&g_acc1[(size_t)gr * 128 + kc]);
            float4 xb = *reinterpret_cast<const float4*>(&g_acc1[(size_t)gr * 128 + kc + 4]);
            hh[0] = __floats2half2_rn(xa.x * sScale[kc]     + sShift[kc],
                                      xa.y * sScale[kc + 1] + sShift[kc + 1]);
            hh[1] = __floats2half2_rn(xa.z * sScale[kc + 2] + sShift[kc + 2],
                                      xa.w * sScale[kc + 3] + sShift[kc + 3]);
            hh[2] = __floats2half2_rn(xb.x * sScale[kc + 4] + sShift[kc + 4],
                                      xb.y * sScale[kc + 5] + sShift[kc + 5]);
            hh[3] = __floats2half2_rn(xb.z * sScale[kc + 6] + sShift[kc + 6],
                                      xb.w * sScale[kc + 7] + sShift[kc + 7]);
        } else {
            hh[0] = hh[1] = hh[2] = hh[3] = __floats2half2_rn(0.f, 0.f);
        }
        *reinterpret_cast<uint4*>(&XH[r * 136 + kc]) = *reinterpret_cast<uint4*>(hh);
    }
    // stage W (fp16): [k][c]
    {
        const __half* wsrc = (ct < 4) ? &g_w2h[ct * 128] : g_wresh;
        int wstride = (ct < 4) ? 512 : 128;
        for (int i = t; i < 2048; i += 256) {
            int k = i >> 4, c8 = (i & 15) * 8;
            *reinterpret_cast<uint4*>(&WH[k * 136 + c8]) =
                *reinterpret_cast<const uint4*>(&wsrc[(size_t)k * wstride + c8]);
        }
    }
    __syncthreads();

    // mainloop: K=128 fully staged, 8 k16 steps
    float d[4][4][4];
    #pragma unroll
    for (int mf = 0; mf < 4; mf++)
        #pragma unroll
        for (int nf = 0; nf < 4; nf++)
            #pragma unroll
            for (int p = 0; p < 4; p++) d[mf][nf][p] = 0.f;

    uint32_t xh_b = smem_u32(XH);
    uint32_t wh_b = smem_u32(WH);
    int arow = lane & 15, acol = (lane >> 4) << 3;
    #pragma unroll
    for (int ks = 0; ks < 8; ks++) {
        int k0 = ks * 16;
        uint32_t a[4][4], b[4][2];
        #pragma unroll
        for (int mf = 0; mf < 4; mf++) {
            int m = warpM * 64 + mf * 16 + arow;
            ldsm_x4(a[mf], xh_b + (uint32_t)(m * 136 + k0 + acol) * 2u);
        }
        #pragma unroll
        for (int nf = 0; nf < 4; nf++) {
            int kk = k0 + (lane & 15);
            int n = warpN * 32 + nf * 8;
            ldsm_x2t(b[nf], wh_b + (uint32_t)(kk * 136 + n) * 2u);
        }
        #pragma unroll
        for (int mf = 0; mf < 4; mf++)
            #pragma unroll
            for (int nf = 0; nf < 4; nf++)
                mma16816(d[mf][nf], a[mf], b[nf]);
    }

    // spill fragments to smem D (fp32), overlaying XH/WH
    __syncthreads();
    #pragma unroll
    for (int mf = 0; mf < 4; mf++)
        #pragma unroll
        for (int nf = 0; nf < 4; nf++) {
            int row = warpM * 64 + mf * 16 + (lane >> 2);
            int col = warpN * 32 + nf * 8 + (lane & 3) * 2;
            *reinterpret_cast<float2*>(&Dsm[row * 130 + col]) =
                make_float2(d[mf][nf][0], d[mf][nf][1]);
            *reinterpret_cast<float2*>(&Dsm[(row + 8) * 130 + col]) =
                make_float2(d[mf][nf][2], d[mf][nf][3]);
        }
    __syncthreads();

    // epilogue (identical structure to proven version, reading Dsm)
    int tc = t & 15, tr = t >> 4;
    if (ct < 4) {
        float av[8], dv[8];
        #pragma unroll
        for (int i = 0; i < 8; i++) {
            av[i] = asrc[ct * 128 + tc * 8 + i];
            dv[i] = adst[ct * 128 + tc * 8 + i];
        }
        #pragma unroll
        for (int j = 0; j < 8; j++) {
            int gr = r0 + tr * 8 + j;
            float o[8];
            const float* dr = &Dsm[(tr * 8 + j) * 130 + tc * 8];
            #pragma unroll
            for (int i = 0; i < 8; i++) o[i] = dr[i];
            int ty = (gr < N) ? nt[gr] : 0;
            const float* bias = &g_ne2w2[ty * 512 + ct * 128 + tc * 8];
            float sp = 0.f, dp = 0.f;
            #pragma unroll
            for (int i = 0; i < 8; i++) {
                o[i] += bias[i];
                sp += o[i] * av[i];
                dp += o[i] * dv[i];
            }
            #pragma unroll
            for (int off = 8; off; off >>= 1) {
                sp += __shfl_xor_sync(0xffffffffu, sp, off);
                dp += __shfl_xor_sync(0xffffffffu, dp, off);
            }
            if (gr < N) {
                __half2 hh[4];
                #pragma unroll
                for (int p = 0; p < 4; p++) hh[p] = __floats2half2_rn(o[2 * p], o[2 * p + 1]);
                *reinterpret_cast<uint4*>(&g_h2h[(size_t)gr * 512 + ct * 128 + tc * 8]) =
                    *reinterpret_cast<uint4*>(hh);
                if (tc == 0) {
                    g_s[gr * 4 + ct] = sp; g_d[gr * 4 + ct] = dp;
                    g_den[gr * 4 + ct] = 0.f;
                }
            }
        }
    } else {
        float4 z4 = make_float4(0.f, 0.f, 0.f, 0.f);
        #pragma unroll
        for (int j = 0; j < 8; j++) {
            int gr = r0 + tr * 8 + j; if (gr >= N) continue;
            float o[8];
            const float* dr = &Dsm[(tr * 8 + j) * 130 + tc * 8];
            #pragma unroll
            for (int i = 0; i < 8; i++) o[i] = dr[i];
            const float* bias = &b2[tc * 8];
            float* dst = &g_res[(size_t)gr * 128 + tc * 8];
            *reinterpret_cast<float4*>(dst) =
                make_float4(o[0] + bias[0], o[1] + bias[1], o[2] + bias[2], o[3] + bias[3]);
            *reinterpret_cast<float4*>(dst + 4) =
                make_float4(o[4] + bias[4], o[5] + bias[5], o[6] + bias[6], o[7] + bias[7]);
            float* az = &g_acc2[(size_t)gr * 128 + tc * 8];
            *reinterpret_cast<float4*>(az)     = z4;
            *reinterpret_cast<float4*>(az + 4) = z4;
        }
    }
}

// ---------------- layer 2 edge pass A (unchanged) ---------------------------------
__global__ void k_edge2A(const int* __restrict__ src, const int* __restrict__ dst, int E) {
    int i = blockIdx.x * blockDim.x + threadIdx.x;
    if (i >= E * 4) return;
    int e = i >> 2, h = i & 3;
    int s_ = src[e], d_ = dst[e];
    float a = g_s[s_ * 4 + h] + g_d[d_ * 4 + h] + g_e2[i];
    a = (a >= 0.f) ? a : 0.2f * a;
    float ex = __expf(a);
    g_alpha[i] = ex;
    atomicAdd(&g_den[d_ * 4 + h], ex);
}

// ---------------- edge aggregate layer 2 (unchanged fp16 version) -----------------
__global__ void k_aggr2(const int* __restrict__ src, const int* __restrict__ dst, int E) {
    int e = blockIdx.x * 8 + (threadIdx.x >> 5); if (e >= E) return;
    int l = threadIdx.x & 31;
    int s_ = src[e], d_ = dst[e];
    float cf = 0.f;
    if (l < 4) cf = 0.25f * g_alpha[e * 4 + l] / (g_den[d_ * 4 + l] + 1e-16f);
    int m = l & 15, hp = l >> 4;
    float ca = __shfl_sync(0xffffffffu, cf, 2 * hp);
    float cb = __shfl_sync(0xffffffffu, cf, 2 * hp + 1);
    const uint4* hs = reinterpret_cast<const uint4*>(&g_h2h[(size_t)s_ * 512]);
    uint4 qa = hs[hp * 32 + m];
    uint4 qb = hs[hp * 32 + 16 + m];
    __half2* pa = reinterpret_cast<__half2*>(&qa);
    __half2* pb = reinterpret_cast<__half2*>(&qb);
    float r[8];
    #pragma unroll
    for (int i = 0; i < 4; i++) {
        float2 fa = __half22float2(pa[i]);
        float2 fb = __half22float2(pb[i]);
        r[2 * i]     = ca * fa.x + cb * fb.x;
        r[2 * i + 1] = ca * fa.y + cb * fb.y;
    }
    #pragma unroll
    for (int i = 0; i < 8; i++) r[i] += __shfl_xor_sync(0xffffffffu, r[i], 16);
    if (l < 16) {
        float* ab = &g_acc2[(size_t)d_ * 128 + m * 8];
        red4(ab,     r[0], r[1], r[2], r[3]);
        red4(ab + 4, r[4], r[5], r[6], r[7]);
    }
}

// ---------------- final: out = acc2 + res2 -----------------------------------------
__global__ void k_final(float4* __restrict__ out, int N) {
    int i = blockIdx.x * blockDim.x + threadIdx.x;
    if (i >= N * 32) return;
    const float4 a = reinterpret_cast<const float4*>(g_acc2)[i];
    const float4 r = reinterpret_cast<const float4*>(g_res)[i];
    out[i] = make_float4(a.x + r.x, a.y + r.y, a.z + r.z, a.w + r.w);
}

// ---------------- host launch ----------------------------------------------------
extern "C" void kernel_launch(void* const* d_in, const int* in_sizes, int n_in,
                              void* d_out, int out_size) {
    const float* x      = (const float*)d_in[0];
    const int*   ei     = (const int*)  d_in[1];
    const int*   nt     = (const int*)  d_in[2];
    const float* ea     = (const float*)d_in[3];
    const int*   et     = (const int*)  d_in[4];
    const float* ne1    = (const float*)d_in[5];
    const float* w1     = (const float*)d_in[6];
    const float* we1    = (const float*)d_in[7];
    const float* asrc1  = (const float*)d_in[8];
    const float* adst1  = (const float*)d_in[9];
    const float* aedge1 = (const float*)d_in[10];
    const float* ee1    = (const float*)d_in[11];
    const float* wres1  = (const float*)d_in[12];
    const float* b1     = (const float*)d_in[13];
    const float* gamma  = (const float*)d_in[14];
    const float* beta   = (const float*)d_in[15];
    const float* ne2    = (const float*)d_in[16];
    const float* w2     = (const float*)d_in[17];
    const float* we2    = (const float*)d_in[18];
    const float* asrc2  = (const float*)d_in[19];
    const float* adst2  = (const float*)d_in[20];
    const float* aedge2 = (const float*)d_in[21];
    const float* ee2    = (const float*)d_in[22];
    const float* wres2  = (const float*)d_in[23];
    const float* b2     = (const float*)d_in[24];

    int N = in_sizes[0] / 32;
    int E = in_sizes[4];
    const int* src = ei;
    const int* dstp = ei + E;

    // ---- precompute ----
    k_pre_a<<<10, 256>>>(we1, aedge1, we2, aedge2, ne1, w1, ne2, w2);
    k_pre_b<<<1, 32>>>(ee1, ee2);
    k_pre_w<<<320, 256>>>(w2, wres2);

    // ---- layer 1 ----
    dim3 g1((N + 127) / 128, 2);
    k_gemm1<<<g1, 256>>>(x, nt, w1, wres1, b1, asrc1, adst1, N);
    k_edge1<<<(E + 31) / 32, 256>>>(src, dstp, ea, et, E);

    // ---- batch norm stats ----
    k_bnstats<<<592, 128>>>(N);

    // ---- layer 2 (tensor-core gemm2) ----
    size_t smem = 70656;
    cudaFuncSetAttribute(k_gemm2, cudaFuncAttributeMaxDynamicSharedMemorySize, (int)smem);
    dim3 g2((N + 127) / 128, 5);
    k_gemm2<<<g2, 256, smem>>>(nt, b2, asrc2, adst2, gamma, beta, N);
    k_edge2A<<<(E * 4 + 255) / 256, 256>>>(src, dstp, E);
    k_aggr2<<<(E + 7) / 8, 256>>>(src, dstp, E);

    // ---- epilogue ----
    k_final<<<(N * 32 + 255) / 256, 256>>>((float4*)d_out, N);
}

// round 12
// speedup vs baseline: 1.3304x; 1.0378x over previous
#include <cuda_runtime.h>
#include <cuda_fp16.h>
#include <math.h>
#include <stdint.h>

// ---------------- problem-size bounds (N=50000, E=400000 in dataset) ----------
#define MAXN 50176
#define MAXE 400384

// ---------------- device scratch (no mallocs allowed) -------------------------
__device__ __half  g_h1h[MAXN * 128];            // layer1 node embeddings (fp16)
__device__ float  g_res [MAXN * 128];            // residual (res1 then res2)
__device__ float  g_acc1[MAXN * 128];            // layer1 aggregate -> y -> BN input
__device__ __half  g_h2h[(size_t)MAXN * 512];    // layer2 node embeddings (fp16)
__device__ float  g_acc2[MAXN * 128];            // layer2 head-averaged aggregate
__device__ float  g_s[MAXN * 4], g_d[MAXN * 4];  // attention src/dst terms
__device__ float  g_den[MAXN * 4];
__device__ float  g_alpha[MAXE * 4];             // layer2 ex values
__device__ float  g_e2[MAXE * 4];                // layer2 edge attention term
__device__ double g_colsum[128], g_colsq[128];
__device__ float  g_aew1T[4 * 64], g_aew2T[4 * 64];  // transposed [h][k]
__device__ float  g_eea1[4 * 4],  g_eea2[4 * 4];
__device__ float  g_ne1w1[3 * 128], g_ne2w2[3 * 512];
__device__ __half g_w2h[128 * 512];              // fp16 copies of weights
__device__ __half g_wresh[128 * 128];
__device__ __half g_w1h[32 * 128];
__device__ __half g_wres1h[32 * 128];

// ---------------- helpers ------------------------------------------------------
__device__ __forceinline__ void red4(float* p, float a, float b, float c, float d) {
    asm volatile("red.global.add.v4.f32 [%0], {%1,%2,%3,%4};"
                 :: "l"(p), "f"(a), "f"(b), "f"(c), "f"(d) : "memory");
}
__device__ __forceinline__ uint32_t smem_u32(const void* p) {
    return (uint32_t)__cvta_generic_to_shared(p);
}
__device__ __forceinline__ void ldsm_x4(uint32_t* r, uint32_t addr) {
    asm volatile("ldmatrix.sync.aligned.m8n8.x4.shared.b16 {%0,%1,%2,%3}, [%4];"
                 : "=r"(r[0]), "=r"(r[1]), "=r"(r[2]), "=r"(r[3]) : "r"(addr));
}
__device__ __forceinline__ void ldsm_x2t(uint32_t* r, uint32_t addr) {
    asm volatile("ldmatrix.sync.aligned.m8n8.x2.trans.shared.b16 {%0,%1}, [%2];"
                 : "=r"(r[0]), "=r"(r[1]) : "r"(addr));
}
__device__ __forceinline__ void mma16816(float* d, const uint32_t* a, const uint32_t* b) {
    asm volatile("mma.sync.aligned.m16n8k16.row.col.f32.f16.f16.f32 "
                 "{%0,%1,%2,%3}, {%4,%5,%6,%7}, {%8,%9}, {%0,%1,%2,%3};"
                 : "+f"(d[0]), "+f"(d[1]), "+f"(d[2]), "+f"(d[3])
                 : "r"(a[0]), "r"(a[1]), "r"(a[2]), "r"(a[3]), "r"(b[0]), "r"(b[1]));
}

// ---------------- precompute: fold linear maps (+ zero colsum) ------------------
__global__ void k_pre_a(const float* __restrict__ we1, const float* __restrict__ aedge1,
                        const float* __restrict__ we2, const float* __restrict__ aedge2,
                        const float* __restrict__ ne1, const float* __restrict__ w1,
                        const float* __restrict__ ne2, const float* __restrict__ w2) {
    int i = blockIdx.x * blockDim.x + threadIdx.x;
    if (i < 128) { g_colsum[i] = 0.0; g_colsq[i] = 0.0; }
    if (i < 256) {
        int k = i >> 2, h = i & 3; float a = 0.f;
        for (int c = 0; c < 32; c++) a += we1[k * 128 + h * 32 + c] * aedge1[h * 32 + c];
        g_aew1T[h * 64 + k] = a;
    } else if (i < 512) {
        int j = i - 256; int k = j >> 2, h = j & 3; float a = 0.f;
        for (int c = 0; c < 128; c++) a += we2[k * 512 + h * 128 + c] * aedge2[h * 128 + c];
        g_aew2T[h * 64 + k] = a;
    } else if (i < 896) {
        int j = i - 512; int t = j >> 7, col = j & 127; float a = 0.f;
        for (int k = 0; k < 32; k++) a += ne1[t * 32 + k] * w1[k * 128 + col];
        g_ne1w1[j] = a;
    } else if (i < 2432) {
        int j = i - 896; int t = j >> 9, col = j & 511; float a = 0.f;
        for (int k = 0; k < 128; k++) a += ne2[t * 128 + k] * w2[k * 512 + col];
        g_ne2w2[j] = a;
    }
}

__global__ void k_pre_b(const float* __restrict__ ee1, const float* __restrict__ ee2) {
    int i = threadIdx.x;
    if (i < 16) {
        int t = i >> 2, h = i & 3; float a = 0.f;
        for (int k = 0; k < 64; k++) a += ee1[t * 64 + k] * g_aew1T[h * 64 + k];
        g_eea1[i] = a;
    } else if (i < 32) {
        int j = i - 16; int t = j >> 2, h = j & 3; float a = 0.f;
        for (int k = 0; k < 64; k++) a += ee2[t * 64 + k] * g_aew2T[h * 64 + k];
        g_eea2[j] = a;
    }
}

// fp16 copies of all weights
__global__ void k_pre_w(const float* __restrict__ w2, const float* __restrict__ wres2,
                        const float* __restrict__ w1, const float* __restrict__ wres1) {
    int i = blockIdx.x * blockDim.x + threadIdx.x;
    if (i < 65536) g_w2h[i] = __float2half(w2[i]);
    else if (i < 81920) g_wresh[i - 65536] = __float2half(wres2[i - 65536]);
    else if (i < 86016) g_w1h[i - 81920] = __float2half(w1[i - 81920]);
    else if (i < 90112) g_wres1h[i - 86016] = __float2half(wres1[i - 86016]);
}

// ---------------- layer 1 GEMM v4: fp16 tensor-core, K=32, fused sd1/zeroing ------
// smem: XH half[128][40] @0 (10240B) | WH half[32][136] @10240 (8704B)
//       Dsm fp32[128][130] overlays @0 after mainloop | sA@66560 sD@67072
__global__ void __launch_bounds__(256, 2)
k_gemm1(const float* __restrict__ x, const int* __restrict__ nt,
        const float* __restrict__ b1,
        const float* __restrict__ asrc, const float* __restrict__ adst, int N) {
    extern __shared__ __align__(16) char smraw[];
    __half* XH = reinterpret_cast<__half*>(smraw);            // [128][40]
    __half* WH = reinterpret_cast<__half*>(smraw + 10240);    // [32][136]
    float*  Dsm = reinterpret_cast<float*>(smraw);            // [128][130] (after)
    float*  sA = reinterpret_cast<float*>(smraw + 66560);
    float*  sD = reinterpret_cast<float*>(smraw + 67072);
    int t = threadIdx.x;           // 256
    int r0 = blockIdx.x * 128;
    int ct = blockIdx.y;           // 0: w1 + sd dots, 1: wres1 + acc zeroing
    int lane = t & 31, w = t >> 5;
    int warpM = w >> 2, warpN = w & 3;

    if (ct == 0 && t < 128) { sA[t] = asrc[t]; sD[t] = adst[t]; }

    // stage X fp16: [r][k], each thread 2 x 8 halves
    for (int i = t; i < 512; i += 256) {
        int r = i >> 2, kc = (i & 3) * 8;
        int gr = r0 + r;
        __half2 hh[4];
        if (gr < N) {
            float4 xa = *reinterpret_cast<const float4*>(&x[(size_t)gr * 32 + kc]);
            float4 xb = *reinterpret_cast<const float4*>(&x[(size_t)gr * 32 + kc + 4]);
            hh[0] = __floats2half2_rn(xa.x, xa.y);
            hh[1] = __floats2half2_rn(xa.z, xa.w);
            hh[2] = __floats2half2_rn(xb.x, xb.y);
            hh[3] = __floats2half2_rn(xb.z, xb.w);
        } else {
            hh[0] = hh[1] = hh[2] = hh[3] = __floats2half2_rn(0.f, 0.f);
        }
        *reinterpret_cast<uint4*>(&XH[r * 40 + kc]) = *reinterpret_cast<uint4*>(hh);
    }
    // stage W fp16: [k:32][c:128]
    {
        const __half* wsrc = ct ? g_wres1h : g_w1h;
        for (int i = t; i < 512; i += 256) {
            int k = i >> 4, c8 = (i & 15) * 8;
            *reinterpret_cast<uint4*>(&WH[k * 136 + c8]) =
                *reinterpret_cast<const uint4*>(&wsrc[k * 128 + c8]);
        }
    }
    __syncthreads();

    float d[4][4][4];
    #pragma unroll
    for (int mf = 0; mf < 4; mf++)
        #pragma unroll
        for (int nf = 0; nf < 4; nf++)
            #pragma unroll
            for (int p = 0; p < 4; p++) d[mf][nf][p] = 0.f;

    uint32_t xh_b = smem_u32(XH);
    uint32_t wh_b = smem_u32(WH);
    int arow = lane & 15, acol = (lane >> 4) << 3;
    #pragma unroll
    for (int ks = 0; ks < 2; ks++) {
        int k0 = ks * 16;
        uint32_t a[4][4], b[4][2];
        #pragma unroll
        for (int mf = 0; mf < 4; mf++) {
            int m = warpM * 64 + mf * 16 + arow;
            ldsm_x4(a[mf], xh_b + (uint32_t)(m * 40 + k0 + acol) * 2u);
        }
        #pragma unroll
        for (int nf = 0; nf < 4; nf++) {
            int kk = k0 + (lane & 15);
            int n = warpN * 32 + nf * 8;
            ldsm_x2t(b[nf], wh_b + (uint32_t)(kk * 136 + n) * 2u);
        }
        #pragma unroll
        for (int mf = 0; mf < 4; mf++)
            #pragma unroll
            for (int nf = 0; nf < 4; nf++)
                mma16816(d[mf][nf], a[mf], b[nf]);
    }

    __syncthreads();
    #pragma unroll
    for (int mf = 0; mf < 4; mf++)
        #pragma unroll
        for (int nf = 0; nf < 4; nf++) {
            int row = warpM * 64 + mf * 16 + (lane >> 2);
            int col = warpN * 32 + nf * 8 + (lane & 3) * 2;
            *reinterpret_cast<float2*>(&Dsm[row * 130 + col]) =
                make_float2(d[mf][nf][0], d[mf][nf][1]);
            *reinterpret_cast<float2*>(&Dsm[(row + 8) * 130 + col]) =
                make_float2(d[mf][nf][2], d[mf][nf][3]);
        }
    __syncthreads();

    int tc = t & 15, tr = t >> 4;
    if (ct == 0) {
        float av[8], dv[8];
        #pragma unroll
        for (int i = 0; i < 8; i++) { av[i] = sA[tc * 8 + i]; dv[i] = sD[tc * 8 + i]; }
        int head = tc >> 2;
        #pragma unroll
        for (int j = 0; j < 8; j++) {
            int gr = r0 + tr * 8 + j;
            float o[8];
            const float* dr = &Dsm[(tr * 8 + j) * 130 + tc * 8];
            #pragma unroll
            for (int i = 0; i < 8; i++) o[i] = dr[i];
            int ty = (gr < N) ? nt[gr] : 0;
            const float* bias = &g_ne1w1[ty * 128 + tc * 8];
            float sp = 0.f, dp = 0.f;
            #pragma unroll
            for (int i = 0; i < 8; i++) {
                o[i] += bias[i];
                sp += o[i] * av[i];
                dp += o[i] * dv[i];
            }
            sp += __shfl_xor_sync(0xffffffffu, sp, 1);
            sp += __shfl_xor_sync(0xffffffffu, sp, 2);
            dp += __shfl_xor_sync(0xffffffffu, dp, 1);
            dp += __shfl_xor_sync(0xffffffffu, dp, 2);
            if (gr < N) {
                __half2 hh[4];
                #pragma unroll
                for (int p = 0; p < 4; p++) hh[p] = __floats2half2_rn(o[2 * p], o[2 * p + 1]);
                *reinterpret_cast<uint4*>(&g_h1h[(size_t)gr * 128 + tc * 8]) =
                    *reinterpret_cast<uint4*>(hh);
                if ((tc & 3) == 0) {
                    g_s[gr * 4 + head] = sp; g_d[gr * 4 + head] = dp;
                    g_den[gr * 4 + head] = 0.f;
                }
            }
        }
    } else {
        float bb[8];
        #pragma unroll
        for (int i = 0; i < 8; i++) bb[i] = b1[tc * 8 + i];
        float4 z4 = make_float4(0.f, 0.f, 0.f, 0.f);
        #pragma unroll
        for (int j = 0; j < 8; j++) {
            int gr = r0 + tr * 8 + j; if (gr >= N) continue;
            float o[8];
            const float* dr = &Dsm[(tr * 8 + j) * 130 + tc * 8];
            #pragma unroll
            for (int i = 0; i < 8; i++) o[i] = dr[i];
            float* dst = &g_res[(size_t)gr * 128 + tc * 8];
            *reinterpret_cast<float4*>(dst) =
                make_float4(o[0] + bb[0], o[1] + bb[1], o[2] + bb[2], o[3] + bb[3]);
            *reinterpret_cast<float4*>(dst + 4) =
                make_float4(o[4] + bb[4], o[5] + bb[5], o[6] + bb[6], o[7] + bb[7]);
            float* az = &g_acc1[(size_t)gr * 128 + tc * 8];
            *reinterpret_cast<float4*>(az)     = z4;
            *reinterpret_cast<float4*>(az + 4) = z4;
        }
    }
}

// ---------------- layer 1 fused edge phase (unchanged best) -----------------------
__global__ void __launch_bounds__(256)
k_edge1(const int* __restrict__ src, const int* __restrict__ dst,
        const float* __restrict__ ea, const int* __restrict__ et, int E) {
    __shared__ __align__(16) float sa1[4][64], sa2[4][64];
    __shared__ float se1[16], se2[16];
    int t = threadIdx.x;
    sa1[t >> 6][t & 63] = g_aew1T[t];
    sa2[t >> 6][t & 63] = g_aew2T[t];
    if (t < 16) { se1[t] = g_eea1[t]; se2[t] = g_eea2[t]; }
    __syncthreads();
    int l = t & 31, li = l & 7;
    int e = blockIdx.x * 32 + (t >> 5) * 4 + (l >> 3);
    bool valid = e < E;
    float e1[4] = {0, 0, 0, 0}, e2[4] = {0, 0, 0, 0};
    int s_ = 0, d_ = 0;
    if (valid) {
        s_ = src[e]; d_ = dst[e];
        const float* row = ea + (size_t)e * 64 + li * 8;
        float4 va = *reinterpret_cast<const float4*>(row);
        float4 vb = *reinterpret_cast<const float4*>(row + 4);
        float vs[8] = {va.x, va.y, va.z, va.w, vb.x, vb.y, vb.z, vb.w};
        #pragma unroll
        for (int h = 0; h < 4; h++) {
            float4 w0 = *reinterpret_cast<const float4*>(&sa1[h][li * 8]);
            float4 w1v = *reinterpret_cast<const float4*>(&sa1[h][li * 8 + 4]);
            float4 u0 = *reinterpret_cast<const float4*>(&sa2[h][li * 8]);
            float4 u1 = *reinterpret_cast<const float4*>(&sa2[h][li * 8 + 4]);
            e1[h] = vs[0]*w0.x + vs[1]*w0.y + vs[2]*w0.z + vs[3]*w0.w
                  + vs[4]*w1v.x + vs[5]*w1v.y + vs[6]*w1v.z + vs[7]*w1v.w;
            e2[h] = vs[0]*u0.x + vs[1]*u0.y + vs[2]*u0.z + vs[3]*u0.w
                  + vs[4]*u1.x + vs[5]*u1.y + vs[6]*u1.z + vs[7]*u1.w;
        }
    }
    #pragma unroll
    for (int h = 0; h < 4; h++)
        #pragma unroll
        for (int o = 1; o < 8; o <<= 1) {
            e1[h] += __shfl_xor_sync(0xffffffffu, e1[h], o);
            e2[h] += __shfl_xor_sync(0xffffffffu, e2[h], o);
        }
    float ex = 0.f;
    if (valid && li < 4) {
        float ev1 = (li == 0) ? e1[0] : (li == 1) ? e1[1] : (li == 2) ? e1[2] : e1[3];
        float ev2 = (li == 0) ? e2[0] : (li == 1) ? e2[1] : (li == 2) ? e2[2] : e2[3];
        int ty = et[e];
        float a = g_s[s_ * 4 + li] + g_d[d_ * 4 + li] + ev1 + se1[ty * 4 + li];
        a = (a >= 0.f) ? a : 0.2f * a;
        ex = __expf(a);
        atomicAdd(&g_den[d_ * 4 + li], ex);
        g_e2[e * 4 + li] = ev2 + se2[ty * 4 + li];
    }
    float exh = __shfl_sync(0xffffffffu, ex, (l & 24) + (li >> 1));
    if (valid) {
        const uint4* hb = reinterpret_cast<const uint4*>(&g_h1h[(size_t)s_ * 128 + li * 16]);
        float* ab = &g_acc1[(size_t)d_ * 128 + li * 16];
        #pragma unroll
        for (int q = 0; q < 2; q++) {
            uint4 pk = hb[q];
            __half2* hp = reinterpret_cast<__half2*>(&pk);
            float2 f0 = __half22float2(hp[0]);
            float2 f1 = __half22float2(hp[1]);
            float2 f2 = __half22float2(hp[2]);
            float2 f3 = __half22float2(hp[3]);
            red4(ab + q * 8,     f0.x * exh, f0.y * exh, f1.x * exh, f1.y * exh);
            red4(ab + q * 8 + 4, f2.x * exh, f2.y * exh, f3.x * exh, f3.y * exh);
        }
    }
}

// ---------------- BN stats (unchanged) --------------------------------------------
__global__ void k_bnstats(int N) {
    int t = threadIdx.x;
    int hh = t >> 5;
    double s = 0.0, q = 0.0;
    for (int n = blockIdx.x; n < N; n += gridDim.x) {
        float den = g_den[n * 4 + hh] + 1e-16f;
        float y = g_acc1[(size_t)n * 128 + t] / den + g_res[(size_t)n * 128 + t];
        g_acc1[(size_t)n * 128 + t] = y;
        s += y; q += (double)y * y;
    }
    atomicAdd(&g_colsum[t], s);
    atomicAdd(&g_colsq[t], q);
}

// ---------------- layer 2 GEMM (unchanged tensor-core version) --------------------
__global__ void __launch_bounds__(256, 2)
k_gemm2(const int* __restrict__ nt, const float* __restrict__ b2,
        const float* __restrict__ asrc, const float* __restrict__ adst,
        const float* __restrict__ gamma, const float* __restrict__ beta, int N) {
    extern __shared__ __align__(16) char smraw[];
    __half* XH = reinterpret_cast<__half*>(smraw);                  // [128][136]
    __half* WH = reinterpret_cast<__half*>(smraw + 34816);          // [128][136]
    float*  Dsm = reinterpret_cast<float*>(smraw);                  // [128][130] (after)
    float*  sScale = reinterpret_cast<float*>(smraw + 69632);
    float*  sShift = reinterpret_cast<float*>(smraw + 70144);
    int t = threadIdx.x;
    int r0 = blockIdx.x * 128;
    int ct = blockIdx.y;
    int lane = t & 31, w = t >> 5;
    int warpM = w >> 2, warpN = w & 3;

    if (t < 128) {
        double mu = g_colsum[t] / N;
        double var = g_colsq[t] / N - mu * mu;
        double sc = (double)gamma[t] / sqrt(var + 1e-5);
        sScale[t] = (float)sc;
        sShift[t] = (float)((double)beta[t] - mu * sc);
    }
    __syncthreads();

    for (int i = t; i < 2048; i += 256) {
        int r = i >> 4, kc = (i & 15) * 8;
        int gr = r0 + r;
        __half2 hh[4];
        if (gr < N) {
            float4 xa = *reinterpret_cast<const float4*>(&g_acc1[(size_t)gr * 128 + kc]);
            float4 xb = *reinterpret_cast<const float4*>(&g_acc1[(size_t)gr * 128 + kc + 4]);
            hh[0] = __floats2half2_rn(xa.x * sScale[kc]     + sShift[kc],
                                      xa.y * sScale[kc + 1] + sShift[kc + 1]);
            hh[1] = __floats2half2_rn(xa.z * sScale[kc + 2] + sShift[kc + 2],
                                      xa.w * sScale[kc + 3] + sShift[kc + 3]);
            hh[2] = __floats2half2_rn(xb.x * sScale[kc + 4] + sShift[kc + 4],
                                      xb.y * sScale[kc + 5] + sShift[kc + 5]);
            hh[3] = __floats2half2_rn(xb.z * sScale[kc + 6] + sShift[kc + 6],
                                      xb.w * sScale[kc + 7] + sShift[kc + 7]);
        } else {
            hh[0] = hh[1] = hh[2] = hh[3] = __floats2half2_rn(0.f, 0.f);
        }
        *reinterpret_cast<uint4*>(&XH[r * 136 + kc]) = *reinterpret_cast<uint4*>(hh);
    }
    {
        const __half* wsrc = (ct < 4) ? &g_w2h[ct * 128] : g_wresh;
        int wstride = (ct < 4) ? 512 : 128;
        for (int i = t; i < 2048; i += 256) {
            int k = i >> 4, c8 = (i & 15) * 8;
            *reinterpret_cast<uint4*>(&WH[k * 136 + c8]) =
                *reinterpret_cast<const uint4*>(&wsrc[(size_t)k * wstride + c8]);
        }
    }
    __syncthreads();

    float d[4][4][4];
    #pragma unroll
    for (int mf = 0; mf < 4; mf++)
        #pragma unroll
        for (int nf = 0; nf < 4; nf++)
            #pragma unroll
            for (int p = 0; p < 4; p++) d[mf][nf][p] = 0.f;

    uint32_t xh_b = smem_u32(XH);
    uint32_t wh_b = smem_u32(WH);
    int arow = lane & 15, acol = (lane >> 4) << 3;
    #pragma unroll
    for (int ks = 0; ks < 8; ks++) {
        int k0 = ks * 16;
        uint32_t a[4][4], b[4][2];
        #pragma unroll
        for (int mf = 0; mf < 4; mf++) {
            int m = warpM * 64 + mf * 16 + arow;
            ldsm_x4(a[mf], xh_b + (uint32_t)(m * 136 + k0 + acol) * 2u);
        }
        #pragma unroll
        for (int nf = 0; nf < 4; nf++) {
            int kk = k0 + (lane & 15);
            int n = warpN * 32 + nf * 8;
            ldsm_x2t(b[nf], wh_b + (uint32_t)(kk * 136 + n) * 2u);
        }
        #pragma unroll
        for (int mf = 0; mf < 4; mf++)
            #pragma unroll
            for (int nf = 0; nf < 4; nf++)
                mma16816(d[mf][nf], a[mf], b[nf]);
    }

    __syncthreads();
    #pragma unroll
    for (int mf = 0; mf < 4; mf++)
        #pragma unroll
        for (int nf = 0; nf < 4; nf++) {
            int row = warpM * 64 + mf * 16 + (lane >> 2);
            int col = warpN * 32 + nf * 8 + (lane & 3) * 2;
            *reinterpret_cast<float2*>(&Dsm[row * 130 + col]) =
                make_float2(d[mf][nf][0], d[mf][nf][1]);
            *reinterpret_cast<float2*>(&Dsm[(row + 8) * 130 + col]) =
                make_float2(d[mf][nf][2], d[mf][nf][3]);
        }
    __syncthreads();

    int tc = t & 15, tr = t >> 4;
    if (ct < 4) {
        float av[8], dv[8];
        #pragma unroll
        for (int i = 0; i < 8; i++) {
            av[i] = asrc[ct * 128 + tc * 8 + i];
            dv[i] = adst[ct * 128 + tc * 8 + i];
        }
        #pragma unroll
        for (int j = 0; j < 8; j++) {
            int gr = r0 + tr * 8 + j;
            float o[8];
            const float* dr = &Dsm[(tr * 8 + j) * 130 + tc * 8];
            #pragma unroll
            for (int i = 0; i < 8; i++) o[i] = dr[i];
            int ty = (gr < N) ? nt[gr] : 0;
            const float* bias = &g_ne2w2[ty * 512 + ct * 128 + tc * 8];
            float sp = 0.f, dp = 0.f;
            #pragma unroll
            for (int i = 0; i < 8; i++) {
                o[i] += bias[i];
                sp += o[i] * av[i];
                dp += o[i] * dv[i];
            }
            #pragma unroll
            for (int off = 8; off; off >>= 1) {
                sp += __shfl_xor_sync(0xffffffffu, sp, off);
                dp += __shfl_xor_sync(0xffffffffu, dp, off);
            }
            if (gr < N) {
                __half2 hh[4];
                #pragma unroll
                for (int p = 0; p < 4; p++) hh[p] = __floats2half2_rn(o[2 * p], o[2 * p + 1]);
                *reinterpret_cast<uint4*>(&g_h2h[(size_t)gr * 512 + ct * 128 + tc * 8]) =
                    *reinterpret_cast<uint4*>(hh);
                if (tc == 0) {
                    g_s[gr * 4 + ct] = sp; g_d[gr * 4 + ct] = dp;
                    g_den[gr * 4 + ct] = 0.f;
                }
            }
        }
    } else {
        float4 z4 = make_float4(0.f, 0.f, 0.f, 0.f);
        #pragma unroll
        for (int j = 0; j < 8; j++) {
            int gr = r0 + tr * 8 + j; if (gr >= N) continue;
            float o[8];
            const float* dr = &Dsm[(tr * 8 + j) * 130 + tc * 8];
            #pragma unroll
            for (int i = 0; i < 8; i++) o[i] = dr[i];
            const float* bias = &b2[tc * 8];
            float* dst = &g_res[(size_t)gr * 128 + tc * 8];
            *reinterpret_cast<float4*>(dst) =
                make_float4(o[0] + bias[0], o[1] + bias[1], o[2] + bias[2], o[3] + bias[3]);
            *reinterpret_cast<float4*>(dst + 4) =
                make_float4(o[4] + bias[4], o[5] + bias[5], o[6] + bias[6], o[7] + bias[7]);
            float* az = &g_acc2[(size_t)gr * 128 + tc * 8];
            *reinterpret_cast<float4*>(az)     = z4;
            *reinterpret_cast<float4*>(az + 4) = z4;
        }
    }
}

// ---------------- layer 2 edge pass A (unchanged) ---------------------------------
__global__ void k_edge2A(const int* __restrict__ src, const int* __restrict__ dst, int E) {
    int i = blockIdx.x * blockDim.x + threadIdx.x;
    if (i >= E * 4) return;
    int e = i >> 2, h = i & 3;
    int s_ = src[e], d_ = dst[e];
    float a = g_s[s_ * 4 + h] + g_d[d_ * 4 + h] + g_e2[i];
    a = (a >= 0.f) ? a : 0.2f * a;
    float ex = __expf(a);
    g_alpha[i] = ex;
    atomicAdd(&g_den[d_ * 4 + h], ex);
}

// ---------------- edge aggregate layer 2 (unchanged fp16 version) -----------------
__global__ void k_aggr2(const int* __restrict__ src, const int* __restrict__ dst, int E) {
    int e = blockIdx.x * 8 + (threadIdx.x >> 5); if (e >= E) return;
    int l = threadIdx.x & 31;
    int s_ = src[e], d_ = dst[e];
    float cf = 0.f;
    if (l < 4) cf = 0.25f * g_alpha[e * 4 + l] / (g_den[d_ * 4 + l] + 1e-16f);
    int m = l & 15, hp = l >> 4;
    float ca = __shfl_sync(0xffffffffu, cf, 2 * hp);
    float cb = __shfl_sync(0xffffffffu, cf, 2 * hp + 1);
    const uint4* hs = reinterpret_cast<const uint4*>(&g_h2h[(size_t)s_ * 512]);
    uint4 qa = hs[hp * 32 + m];
    uint4 qb = hs[hp * 32 + 16 + m];
    __half2* pa = reinterpret_cast<__half2*>(&qa);
    __half2* pb = reinterpret_cast<__half2*>(&qb);
    float r[8];
    #pragma unroll
    for (int i = 0; i < 4; i++) {
        float2 fa = __half22float2(pa[i]);
        float2 fb = __half22float2(pb[i]);
        r[2 * i]     = ca * fa.x + cb * fb.x;
        r[2 * i + 1] = ca * fa.y + cb * fb.y;
    }
    #pragma unroll
    for (int i = 0; i < 8; i++) r[i] += __shfl_xor_sync(0xffffffffu, r[i], 16);
    if (l < 16) {
        float* ab = &g_acc2[(size_t)d_ * 128 + m * 8];
        red4(ab,     r[0], r[1], r[2], r[3]);
        red4(ab + 4, r[4], r[5], r[6], r[7]);
    }
}

// ---------------- final: out = acc2 + res2 -----------------------------------------
__global__ void k_final(float4* __restrict__ out, int N) {
    int i = blockIdx.x * blockDim.x + threadIdx.x;
    if (i >= N * 32) return;
    const float4 a = reinterpret_cast<const float4*>(g_acc2)[i];
    const float4 r = reinterpret_cast<const float4*>(g_res)[i];
    out[i] = make_float4(a.x + r.x, a.y + r.y, a.z + r.z, a.w + r.w);
}

// ---------------- host launch ----------------------------------------------------
extern "C" void kernel_launch(void* const* d_in, const int* in_sizes, int n_in,
                              void* d_out, int out_size) {
    const float* x      = (const float*)d_in[0];
    const int*   ei     = (const int*)  d_in[1];
    const int*   nt     = (const int*)  d_in[2];
    const float* ea     = (const float*)d_in[3];
    const int*   et     = (const int*)  d_in[4];
    const float* ne1    = (const float*)d_in[5];
    const float* w1     = (const float*)d_in[6];
    const float* we1    = (const float*)d_in[7];
    const float* asrc1  = (const float*)d_in[8];
    const float* adst1  = (const float*)d_in[9];
    const float* aedge1 = (const float*)d_in[10];
    const float* ee1    = (const float*)d_in[11];
    const float* wres1  = (const float*)d_in[12];
    const float* b1     = (const float*)d_in[13];
    const float* gamma  = (const float*)d_in[14];
    const float* beta   = (const float*)d_in[15];
    const float* ne2    = (const float*)d_in[16];
    const float* w2     = (const float*)d_in[17];
    const float* we2    = (const float*)d_in[18];
    const float* asrc2  = (const float*)d_in[19];
    const float* adst2  = (const float*)d_in[20];
    const float* aedge2 = (const float*)d_in[21];
    const float* ee2    = (const float*)d_in[22];
    const float* wres2  = (const float*)d_in[23];
    const float* b2     = (const float*)d_in[24];

    int N = in_sizes[0] / 32;
    int E = in_sizes[4];
    const int* src = ei;
    const int* dstp = ei + E;

    // ---- precompute ----
    k_pre_a<<<10, 256>>>(we1, aedge1, we2, aedge2, ne1, w1, ne2, w2);
    k_pre_b<<<1, 32>>>(ee1, ee2);
    k_pre_w<<<352, 256>>>(w2, wres2, w1, wres1);

    // ---- layer 1 (tensor-core gemm1) ----
    size_t smem1 = 67584;
    cudaFuncSetAttribute(k_gemm1, cudaFuncAttributeMaxDynamicSharedMemorySize, (int)smem1);
    dim3 g1((N + 127) / 128, 2);
    k_gemm1<<<g1, 256, smem1>>>(x, nt, b1, asrc1, adst1, N);
    k_edge1<<<(E + 31) / 32, 256>>>(src, dstp, ea, et, E);

    // ---- batch norm stats ----
    k_bnstats<<<592, 128>>>(N);

    // ---- layer 2 (tensor-core gemm2) ----
    size_t smem2 = 70656;
    cudaFuncSetAttribute(k_gemm2, cudaFuncAttributeMaxDynamicSharedMemorySize, (int)smem2);
    dim3 g2((N + 127) / 128, 5);
    k_gemm2<<<g2, 256, smem2>>>(nt, b2, asrc2, adst2, gamma, beta, N);
    k_edge2A<<<(E * 4 + 255) / 256, 256>>>(src, dstp, E);
    k_aggr2<<<(E + 7) / 8, 256>>>(src, dstp, E);

    // ---- epilogue ----
    k_final<<<(N * 32 + 255) / 256, 256>>>((float4*)d_out, N);
}

// round 13
// speedup vs baseline: 1.4114x; 1.0609x over previous
#include <cuda_runtime.h>
#include <cuda_fp16.h>
#include <math.h>
#include <stdint.h>

// ---------------- problem-size bounds (N=50000, E=400000 in dataset) ----------
#define MAXN 50176
#define MAXE 400384

// ---------------- device scratch (no mallocs allowed) -------------------------
__device__ __half  g_h1h[MAXN * 128];            // layer1 node embeddings (fp16)
__device__ float  g_res [MAXN * 128];            // residual res1
__device__ float  g_acc1[MAXN * 128];            // layer1 aggregate -> y -> BN input
__device__ __half  g_xh2[MAXN * 128];            // BN(y) fp16 (gemm2 input)
__device__ __half  g_h2h[(size_t)MAXN * 512];    // layer2 node embeddings (fp16)
__device__ float  g_s[MAXN * 4], g_d[MAXN * 4];  // attention src/dst terms
__device__ float  g_den[MAXN * 4];
__device__ float  g_alpha[MAXE * 4];             // layer2 ex values
__device__ float  g_e2[MAXE * 4];                // layer2 edge attention term
__device__ double g_colsum[128], g_colsq[128];
__device__ float  g_scale[128], g_shift[128];
__device__ float  g_aew1T[4 * 64], g_aew2T[4 * 64];  // transposed [h][k]
__device__ float  g_eea1[4 * 4],  g_eea2[4 * 4];
__device__ float  g_ne1w1[3 * 128], g_ne2w2[3 * 512];
__device__ __half g_w2h[128 * 512];              // fp16 copies of weights
__device__ __half g_wresh[128 * 128];
__device__ __half g_w1h[32 * 128];
__device__ __half g_wres1h[32 * 128];

// ---------------- helpers ------------------------------------------------------
__device__ __forceinline__ void red4(float* p, float a, float b, float c, float d) {
    asm volatile("red.global.add.v4.f32 [%0], {%1,%2,%3,%4};"
                 :: "l"(p), "f"(a), "f"(b), "f"(c), "f"(d) : "memory");
}
__device__ __forceinline__ uint32_t smem_u32(const void* p) {
    return (uint32_t)__cvta_generic_to_shared(p);
}
__device__ __forceinline__ void ldsm_x4(uint32_t* r, uint32_t addr) {
    asm volatile("ldmatrix.sync.aligned.m8n8.x4.shared.b16 {%0,%1,%2,%3}, [%4];"
                 : "=r"(r[0]), "=r"(r[1]), "=r"(r[2]), "=r"(r[3]) : "r"(addr));
}
__device__ __forceinline__ void ldsm_x2t(uint32_t* r, uint32_t addr) {
    asm volatile("ldmatrix.sync.aligned.m8n8.x2.trans.shared.b16 {%0,%1}, [%2];"
                 : "=r"(r[0]), "=r"(r[1]) : "r"(addr));
}
__device__ __forceinline__ void mma16816(float* d, const uint32_t* a, const uint32_t* b) {
    asm volatile("mma.sync.aligned.m16n8k16.row.col.f32.f16.f16.f32 "
                 "{%0,%1,%2,%3}, {%4,%5,%6,%7}, {%8,%9}, {%0,%1,%2,%3};"
                 : "+f"(d[0]), "+f"(d[1]), "+f"(d[2]), "+f"(d[3])
                 : "r"(a[0]), "r"(a[1]), "r"(a[2]), "r"(a[3]), "r"(b[0]), "r"(b[1]));
}

// ---------------- precompute: fold linear maps (+ zero colsum) ------------------
__global__ void k_pre_a(const float* __restrict__ we1, const float* __restrict__ aedge1,
                        const float* __restrict__ we2, const float* __restrict__ aedge2,
                        const float* __restrict__ ne1, const float* __restrict__ w1,
                        const float* __restrict__ ne2, const float* __restrict__ w2) {
    int i = blockIdx.x * blockDim.x + threadIdx.x;
    if (i < 128) { g_colsum[i] = 0.0; g_colsq[i] = 0.0; }
    if (i < 256) {
        int k = i >> 2, h = i & 3; float a = 0.f;
        for (int c = 0; c < 32; c++) a += we1[k * 128 + h * 32 + c] * aedge1[h * 32 + c];
        g_aew1T[h * 64 + k] = a;
    } else if (i < 512) {
        int j = i - 256; int k = j >> 2, h = j & 3; float a = 0.f;
        for (int c = 0; c < 128; c++) a += we2[k * 512 + h * 128 + c] * aedge2[h * 128 + c];
        g_aew2T[h * 64 + k] = a;
    } else if (i < 896) {
        int j = i - 512; int t = j >> 7, col = j & 127; float a = 0.f;
        for (int k = 0; k < 32; k++) a += ne1[t * 32 + k] * w1[k * 128 + col];
        g_ne1w1[j] = a;
    } else if (i < 2432) {
        int j = i - 896; int t = j >> 9, col = j & 511; float a = 0.f;
        for (int k = 0; k < 128; k++) a += ne2[t * 128 + k] * w2[k * 512 + col];
        g_ne2w2[j] = a;
    }
}

__global__ void k_pre_b(const float* __restrict__ ee1, const float* __restrict__ ee2) {
    int i = threadIdx.x;
    if (i < 16) {
        int t = i >> 2, h = i & 3; float a = 0.f;
        for (int k = 0; k < 64; k++) a += ee1[t * 64 + k] * g_aew1T[h * 64 + k];
        g_eea1[i] = a;
    } else if (i < 32) {
        int j = i - 16; int t = j >> 2, h = j & 3; float a = 0.f;
        for (int k = 0; k < 64; k++) a += ee2[t * 64 + k] * g_aew2T[h * 64 + k];
        g_eea2[j] = a;
    }
}

// fp16 copies of all weights
__global__ void k_pre_w(const float* __restrict__ w2, const float* __restrict__ wres2,
                        const float* __restrict__ w1, const float* __restrict__ wres1) {
    int i = blockIdx.x * blockDim.x + threadIdx.x;
    if (i < 65536) g_w2h[i] = __float2half(w2[i]);
    else if (i < 81920) g_wresh[i - 65536] = __float2half(wres2[i - 65536]);
    else if (i < 86016) g_w1h[i - 81920] = __float2half(w1[i - 81920]);
    else if (i < 90112) g_wres1h[i - 86016] = __float2half(wres1[i - 86016]);
}

// ---------------- layer 1 GEMM: fp16 tensor-core, K=32, fused sd1/zeroing ---------
__global__ void __launch_bounds__(256, 2)
k_gemm1(const float* __restrict__ x, const int* __restrict__ nt,
        const float* __restrict__ b1,
        const float* __restrict__ asrc, const float* __restrict__ adst, int N) {
    extern __shared__ __align__(16) char smraw[];
    __half* XH = reinterpret_cast<__half*>(smraw);            // [128][40]
    __half* WH = reinterpret_cast<__half*>(smraw + 10240);    // [32][136]
    float*  Dsm = reinterpret_cast<float*>(smraw);            // [128][130] (after)
    float*  sA = reinterpret_cast<float*>(smraw + 66560);
    float*  sD = reinterpret_cast<float*>(smraw + 67072);
    int t = threadIdx.x;           // 256
    int r0 = blockIdx.x * 128;
    int ct = blockIdx.y;           // 0: w1 + sd dots, 1: wres1 + acc zeroing
    int lane = t & 31, w = t >> 5;
    int warpM = w >> 2, warpN = w & 3;

    if (ct == 0 && t < 128) { sA[t] = asrc[t]; sD[t] = adst[t]; }

    for (int i = t; i < 512; i += 256) {
        int r = i >> 2, kc = (i & 3) * 8;
        int gr = r0 + r;
        __half2 hh[4];
        if (gr < N) {
            float4 xa = *reinterpret_cast<const float4*>(&x[(size_t)gr * 32 + kc]);
            float4 xb = *reinterpret_cast<const float4*>(&x[(size_t)gr * 32 + kc + 4]);
            hh[0] = __floats2half2_rn(xa.x, xa.y);
            hh[1] = __floats2half2_rn(xa.z, xa.w);
            hh[2] = __floats2half2_rn(xb.x, xb.y);
            hh[3] = __floats2half2_rn(xb.z, xb.w);
        } else {
            hh[0] = hh[1] = hh[2] = hh[3] = __floats2half2_rn(0.f, 0.f);
        }
        *reinterpret_cast<uint4*>(&XH[r * 40 + kc]) = *reinterpret_cast<uint4*>(hh);
    }
    {
        const __half* wsrc = ct ? g_wres1h : g_w1h;
        for (int i = t; i < 512; i += 256) {
            int k = i >> 4, c8 = (i & 15) * 8;
            *reinterpret_cast<uint4*>(&WH[k * 136 + c8]) =
                *reinterpret_cast<const uint4*>(&wsrc[k * 128 + c8]);
        }
    }
    __syncthreads();

    float d[4][4][4];
    #pragma unroll
    for (int mf = 0; mf < 4; mf++)
        #pragma unroll
        for (int nf = 0; nf < 4; nf++)
            #pragma unroll
            for (int p = 0; p < 4; p++) d[mf][nf][p] = 0.f;

    uint32_t xh_b = smem_u32(XH);
    uint32_t wh_b = smem_u32(WH);
    int arow = lane & 15, acol = (lane >> 4) << 3;
    #pragma unroll
    for (int ks = 0; ks < 2; ks++) {
        int k0 = ks * 16;
        uint32_t a[4][4], b[4][2];
        #pragma unroll
        for (int mf = 0; mf < 4; mf++) {
            int m = warpM * 64 + mf * 16 + arow;
            ldsm_x4(a[mf], xh_b + (uint32_t)(m * 40 + k0 + acol) * 2u);
        }
        #pragma unroll
        for (int nf = 0; nf < 4; nf++) {
            int kk = k0 + (lane & 15);
            int n = warpN * 32 + nf * 8;
            ldsm_x2t(b[nf], wh_b + (uint32_t)(kk * 136 + n) * 2u);
        }
        #pragma unroll
        for (int mf = 0; mf < 4; mf++)
            #pragma unroll
            for (int nf = 0; nf < 4; nf++)
                mma16816(d[mf][nf], a[mf], b[nf]);
    }

    __syncthreads();
    #pragma unroll
    for (int mf = 0; mf < 4; mf++)
        #pragma unroll
        for (int nf = 0; nf < 4; nf++) {
            int row = warpM * 64 + mf * 16 + (lane >> 2);
            int col = warpN * 32 + nf * 8 + (lane & 3) * 2;
            *reinterpret_cast<float2*>(&Dsm[row * 130 + col]) =
                make_float2(d[mf][nf][0], d[mf][nf][1]);
            *reinterpret_cast<float2*>(&Dsm[(row + 8) * 130 + col]) =
                make_float2(d[mf][nf][2], d[mf][nf][3]);
        }
    __syncthreads();

    int tc = t & 15, tr = t >> 4;
    if (ct == 0) {
        float av[8], dv[8];
        #pragma unroll
        for (int i = 0; i < 8; i++) { av[i] = sA[tc * 8 + i]; dv[i] = sD[tc * 8 + i]; }
        int head = tc >> 2;
        #pragma unroll
        for (int j = 0; j < 8; j++) {
            int gr = r0 + tr * 8 + j;
            float o[8];
            const float* dr = &Dsm[(tr * 8 + j) * 130 + tc * 8];
            #pragma unroll
            for (int i = 0; i < 8; i++) o[i] = dr[i];
            int ty = (gr < N) ? nt[gr] : 0;
            const float* bias = &g_ne1w1[ty * 128 + tc * 8];
            float sp = 0.f, dp = 0.f;
            #pragma unroll
            for (int i = 0; i < 8; i++) {
                o[i] += bias[i];
                sp += o[i] * av[i];
                dp += o[i] * dv[i];
            }
            sp += __shfl_xor_sync(0xffffffffu, sp, 1);
            sp += __shfl_xor_sync(0xffffffffu, sp, 2);
            dp += __shfl_xor_sync(0xffffffffu, dp, 1);
            dp += __shfl_xor_sync(0xffffffffu, dp, 2);
            if (gr < N) {
                __half2 hh[4];
                #pragma unroll
                for (int p = 0; p < 4; p++) hh[p] = __floats2half2_rn(o[2 * p], o[2 * p + 1]);
                *reinterpret_cast<uint4*>(&g_h1h[(size_t)gr * 128 + tc * 8]) =
                    *reinterpret_cast<uint4*>(hh);
                if ((tc & 3) == 0) {
                    g_s[gr * 4 + head] = sp; g_d[gr * 4 + head] = dp;
                    g_den[gr * 4 + head] = 0.f;
                }
            }
        }
    } else {
        float bb[8];
        #pragma unroll
        for (int i = 0; i < 8; i++) bb[i] = b1[tc * 8 + i];
        float4 z4 = make_float4(0.f, 0.f, 0.f, 0.f);
        #pragma unroll
        for (int j = 0; j < 8; j++) {
            int gr = r0 + tr * 8 + j; if (gr >= N) continue;
            float o[8];
            const float* dr = &Dsm[(tr * 8 + j) * 130 + tc * 8];
            #pragma unroll
            for (int i = 0; i < 8; i++) o[i] = dr[i];
            float* dst = &g_res[(size_t)gr * 128 + tc * 8];
            *reinterpret_cast<float4*>(dst) =
                make_float4(o[0] + bb[0], o[1] + bb[1], o[2] + bb[2], o[3] + bb[3]);
            *reinterpret_cast<float4*>(dst + 4) =
                make_float4(o[4] + bb[4], o[5] + bb[5], o[6] + bb[6], o[7] + bb[7]);
            float* az = &g_acc1[(size_t)gr * 128 + tc * 8];
            *reinterpret_cast<float4*>(az)     = z4;
            *reinterpret_cast<float4*>(az + 4) = z4;
        }
    }
}

// ---------------- layer 1 fused edge phase (unchanged best) -----------------------
__global__ void __launch_bounds__(256)
k_edge1(const int* __restrict__ src, const int* __restrict__ dst,
        const float* __restrict__ ea, const int* __restrict__ et, int E) {
    __shared__ __align__(16) float sa1[4][64], sa2[4][64];
    __shared__ float se1[16], se2[16];
    int t = threadIdx.x;
    sa1[t >> 6][t & 63] = g_aew1T[t];
    sa2[t >> 6][t & 63] = g_aew2T[t];
    if (t < 16) { se1[t] = g_eea1[t]; se2[t] = g_eea2[t]; }
    __syncthreads();
    int l = t & 31, li = l & 7;
    int e = blockIdx.x * 32 + (t >> 5) * 4 + (l >> 3);
    bool valid = e < E;
    float e1[4] = {0, 0, 0, 0}, e2[4] = {0, 0, 0, 0};
    int s_ = 0, d_ = 0;
    if (valid) {
        s_ = src[e]; d_ = dst[e];
        const float* row = ea + (size_t)e * 64 + li * 8;
        float4 va = *reinterpret_cast<const float4*>(row);
        float4 vb = *reinterpret_cast<const float4*>(row + 4);
        float vs[8] = {va.x, va.y, va.z, va.w, vb.x, vb.y, vb.z, vb.w};
        #pragma unroll
        for (int h = 0; h < 4; h++) {
            float4 w0 = *reinterpret_cast<const float4*>(&sa1[h][li * 8]);
            float4 w1v = *reinterpret_cast<const float4*>(&sa1[h][li * 8 + 4]);
            float4 u0 = *reinterpret_cast<const float4*>(&sa2[h][li * 8]);
            float4 u1 = *reinterpret_cast<const float4*>(&sa2[h][li * 8 + 4]);
            e1[h] = vs[0]*w0.x + vs[1]*w0.y + vs[2]*w0.z + vs[3]*w0.w
                  + vs[4]*w1v.x + vs[5]*w1v.y + vs[6]*w1v.z + vs[7]*w1v.w;
            e2[h] = vs[0]*u0.x + vs[1]*u0.y + vs[2]*u0.z + vs[3]*u0.w
                  + vs[4]*u1.x + vs[5]*u1.y + vs[6]*u1.z + vs[7]*u1.w;
        }
    }
    #pragma unroll
    for (int h = 0; h < 4; h++)
        #pragma unroll
        for (int o = 1; o < 8; o <<= 1) {
            e1[h] += __shfl_xor_sync(0xffffffffu, e1[h], o);
            e2[h] += __shfl_xor_sync(0xffffffffu, e2[h], o);
        }
    float ex = 0.f;
    if (valid && li < 4) {
        float ev1 = (li == 0) ? e1[0] : (li == 1) ? e1[1] : (li == 2) ? e1[2] : e1[3];
        float ev2 = (li == 0) ? e2[0] : (li == 1) ? e2[1] : (li == 2) ? e2[2] : e2[3];
        int ty = et[e];
        float a = g_s[s_ * 4 + li] + g_d[d_ * 4 + li] + ev1 + se1[ty * 4 + li];
        a = (a >= 0.f) ? a : 0.2f * a;
        ex = __expf(a);
        atomicAdd(&g_den[d_ * 4 + li], ex);
        g_e2[e * 4 + li] = ev2 + se2[ty * 4 + li];
    }
    float exh = __shfl_sync(0xffffffffu, ex, (l & 24) + (li >> 1));
    if (valid) {
        const uint4* hb = reinterpret_cast<const uint4*>(&g_h1h[(size_t)s_ * 128 + li * 16]);
        float* ab = &g_acc1[(size_t)d_ * 128 + li * 16];
        #pragma unroll
        for (int q = 0; q < 2; q++) {
            uint4 pk = hb[q];
            __half2* hp = reinterpret_cast<__half2*>(&pk);
            float2 f0 = __half22float2(hp[0]);
            float2 f1 = __half22float2(hp[1]);
            float2 f2 = __half22float2(hp[2]);
            float2 f3 = __half22float2(hp[3]);
            red4(ab + q * 8,     f0.x * exh, f0.y * exh, f1.x * exh, f1.y * exh);
            red4(ab + q * 8 + 4, f2.x * exh, f2.y * exh, f3.x * exh, f3.y * exh);
        }
    }
}

// ---------------- BN stats: y = acc1/den + res (softmax norm fused) --------------
__global__ void k_bnstats(int N) {
    int t = threadIdx.x;
    int hh = t >> 5;
    double s = 0.0, q = 0.0;
    for (int n = blockIdx.x; n < N; n += gridDim.x) {
        float den = g_den[n * 4 + hh] + 1e-16f;
        float y = g_acc1[(size_t)n * 128 + t] / den + g_res[(size_t)n * 128 + t];
        g_acc1[(size_t)n * 128 + t] = y;
        s += y; q += (double)y * y;
    }
    atomicAdd(&g_colsum[t], s);
    atomicAdd(&g_colsq[t], q);
}

__global__ void k_bnfin(const float* __restrict__ gamma, const float* __restrict__ beta, int N) {
    int t = threadIdx.x;
    double mu = g_colsum[t] / N;
    double var = g_colsq[t] / N - mu * mu;
    double sc = (double)gamma[t] / sqrt(var + 1e-5);
    g_scale[t] = (float)sc;
    g_shift[t] = (float)((double)beta[t] - mu * sc);
}

// apply BN once, write fp16 gemm2 input
__global__ void k_bnapply(int N) {
    int i = blockIdx.x * blockDim.x + threadIdx.x;   // one uint4 (8 halves) per thread
    if (i >= N * 16) return;
    int kc = (i & 15) * 8;
    size_t base = (size_t)(i >> 4) * 128 + kc;
    float4 xa = *reinterpret_cast<const float4*>(&g_acc1[base]);
    float4 xb = *reinterpret_cast<const float4*>(&g_acc1[base + 4]);
    __half2 hh[4];
    hh[0] = __floats2half2_rn(xa.x * g_scale[kc]     + g_shift[kc],
                              xa.y * g_scale[kc + 1] + g_shift[kc + 1]);
    hh[1] = __floats2half2_rn(xa.z * g_scale[kc + 2] + g_shift[kc + 2],
                              xa.w * g_scale[kc + 3] + g_shift[kc + 3]);
    hh[2] = __floats2half2_rn(xb.x * g_scale[kc + 4] + g_shift[kc + 4],
                              xb.y * g_scale[kc + 5] + g_shift[kc + 5]);
    hh[3] = __floats2half2_rn(xb.z * g_scale[kc + 6] + g_shift[kc + 6],
                              xb.w * g_scale[kc + 7] + g_shift[kc + 7]);
    *reinterpret_cast<uint4*>(&g_xh2[base]) = *reinterpret_cast<uint4*>(hh);
}

// ---------------- layer 2 GEMM: fp16 tensor-core; ct=4 writes res2 -> d_out -------
__global__ void __launch_bounds__(256, 2)
k_gemm2(const int* __restrict__ nt, const float* __restrict__ b2,
        const float* __restrict__ asrc, const float* __restrict__ adst,
        float* __restrict__ outp, int N) {
    extern __shared__ __align__(16) char smraw[];
    __half* XH = reinterpret_cast<__half*>(smraw);                  // [128][136]
    __half* WH = reinterpret_cast<__half*>(smraw + 34816);          // [128][136]
    float*  Dsm = reinterpret_cast<float*>(smraw);                  // [128][130] (after)
    int t = threadIdx.x;
    int r0 = blockIdx.x * 128;
    int ct = blockIdx.y;
    int lane = t & 31, w = t >> 5;
    int warpM = w >> 2, warpN = w & 3;

    // stage X fp16 from precomputed BN'd array
    for (int i = t; i < 2048; i += 256) {
        int r = i >> 4, c8 = (i & 15) * 8;
        int gr = r0 + r;
        uint4 v = make_uint4(0u, 0u, 0u, 0u);
        if (gr < N) v = *reinterpret_cast<const uint4*>(&g_xh2[(size_t)gr * 128 + c8]);
        *reinterpret_cast<uint4*>(&XH[r * 136 + c8]) = v;
    }
    {
        const __half* wsrc = (ct < 4) ? &g_w2h[ct * 128] : g_wresh;
        int wstride = (ct < 4) ? 512 : 128;
        for (int i = t; i < 2048; i += 256) {
            int k = i >> 4, c8 = (i & 15) * 8;
            *reinterpret_cast<uint4*>(&WH[k * 136 + c8]) =
                *reinterpret_cast<const uint4*>(&wsrc[(size_t)k * wstride + c8]);
        }
    }
    __syncthreads();

    float d[4][4][4];
    #pragma unroll
    for (int mf = 0; mf < 4; mf++)
        #pragma unroll
        for (int nf = 0; nf < 4; nf++)
            #pragma unroll
            for (int p = 0; p < 4; p++) d[mf][nf][p] = 0.f;

    uint32_t xh_b = smem_u32(XH);
    uint32_t wh_b = smem_u32(WH);
    int arow = lane & 15, acol = (lane >> 4) << 3;
    #pragma unroll
    for (int ks = 0; ks < 8; ks++) {
        int k0 = ks * 16;
        uint32_t a[4][4], b[4][2];
        #pragma unroll
        for (int mf = 0; mf < 4; mf++) {
            int m = warpM * 64 + mf * 16 + arow;
            ldsm_x4(a[mf], xh_b + (uint32_t)(m * 136 + k0 + acol) * 2u);
        }
        #pragma unroll
        for (int nf = 0; nf < 4; nf++) {
            int kk = k0 + (lane & 15);
            int n = warpN * 32 + nf * 8;
            ldsm_x2t(b[nf], wh_b + (uint32_t)(kk * 136 + n) * 2u);
        }
        #pragma unroll
        for (int mf = 0; mf < 4; mf++)
            #pragma unroll
            for (int nf = 0; nf < 4; nf++)
                mma16816(d[mf][nf], a[mf], b[nf]);
    }

    __syncthreads();
    #pragma unroll
    for (int mf = 0; mf < 4; mf++)
        #pragma unroll
        for (int nf = 0; nf < 4; nf++) {
            int row = warpM * 64 + mf * 16 + (lane >> 2);
            int col = warpN * 32 + nf * 8 + (lane & 3) * 2;
            *reinterpret_cast<float2*>(&Dsm[row * 130 + col]) =
                make_float2(d[mf][nf][0], d[mf][nf][1]);
            *reinterpret_cast<float2*>(&Dsm[(row + 8) * 130 + col]) =
                make_float2(d[mf][nf][2], d[mf][nf][3]);
        }
    __syncthreads();

    int tc = t & 15, tr = t >> 4;
    if (ct < 4) {
        float av[8], dv[8];
        #pragma unroll
        for (int i = 0; i < 8; i++) {
            av[i] = asrc[ct * 128 + tc * 8 + i];
            dv[i] = adst[ct * 128 + tc * 8 + i];
        }
        #pragma unroll
        for (int j = 0; j < 8; j++) {
            int gr = r0 + tr * 8 + j;
            float o[8];
            const float* dr = &Dsm[(tr * 8 + j) * 130 + tc * 8];
            #pragma unroll
            for (int i = 0; i < 8; i++) o[i] = dr[i];
            int ty = (gr < N) ? nt[gr] : 0;
            const float* bias = &g_ne2w2[ty * 512 + ct * 128 + tc * 8];
            float sp = 0.f, dp = 0.f;
            #pragma unroll
            for (int i = 0; i < 8; i++) {
                o[i] += bias[i];
                sp += o[i] * av[i];
                dp += o[i] * dv[i];
            }
            #pragma unroll
            for (int off = 8; off; off >>= 1) {
                sp += __shfl_xor_sync(0xffffffffu, sp, off);
                dp += __shfl_xor_sync(0xffffffffu, dp, off);
            }
            if (gr < N) {
                __half2 hh[4];
                #pragma unroll
                for (int p = 0; p < 4; p++) hh[p] = __floats2half2_rn(o[2 * p], o[2 * p + 1]);
                *reinterpret_cast<uint4*>(&g_h2h[(size_t)gr * 512 + ct * 128 + tc * 8]) =
                    *reinterpret_cast<uint4*>(hh);
                if (tc == 0) {
                    g_s[gr * 4 + ct] = sp; g_d[gr * 4 + ct] = dp;
                    g_den[gr * 4 + ct] = 0.f;
                }
            }
        }
    } else {
        // res2 + b2 written directly into d_out; aggr2 red4-accumulates on top
        #pragma unroll
        for (int j = 0; j < 8; j++) {
            int gr = r0 + tr * 8 + j; if (gr >= N) continue;
            float o[8];
            const float* dr = &Dsm[(tr * 8 + j) * 130 + tc * 8];
            #pragma unroll
            for (int i = 0; i < 8; i++) o[i] = dr[i];
            const float* bias = &b2[tc * 8];
            float* dst = &outp[(size_t)gr * 128 + tc * 8];
            *reinterpret_cast<float4*>(dst) =
                make_float4(o[0] + bias[0], o[1] + bias[1], o[2] + bias[2], o[3] + bias[3]);
            *reinterpret_cast<float4*>(dst + 4) =
                make_float4(o[4] + bias[4], o[5] + bias[5], o[6] + bias[6], o[7] + bias[7]);
        }
    }
}

// ---------------- layer 2 edge pass A (unchanged) ---------------------------------
__global__ void k_edge2A(const int* __restrict__ src, const int* __restrict__ dst, int E) {
    int i = blockIdx.x * blockDim.x + threadIdx.x;
    if (i >= E * 4) return;
    int e = i >> 2, h = i & 3;
    int s_ = src[e], d_ = dst[e];
    float a = g_s[s_ * 4 + h] + g_d[d_ * 4 + h] + g_e2[i];
    a = (a >= 0.f) ? a : 0.2f * a;
    float ex = __expf(a);
    g_alpha[i] = ex;
    atomicAdd(&g_den[d_ * 4 + h], ex);
}

// ---------------- edge aggregate layer 2: red4 directly into d_out ----------------
__global__ void k_aggr2(const int* __restrict__ src, const int* __restrict__ dst,
                        float* __restrict__ outp, int E) {
    int e = blockIdx.x * 8 + (threadIdx.x >> 5); if (e >= E) return;
    int l = threadIdx.x & 31;
    int s_ = src[e], d_ = dst[e];
    float cf = 0.f;
    if (l < 4) cf = 0.25f * g_alpha[e * 4 + l] / (g_den[d_ * 4 + l] + 1e-16f);
    int m = l & 15, hp = l >> 4;
    float ca = __shfl_sync(0xffffffffu, cf, 2 * hp);
    float cb = __shfl_sync(0xffffffffu, cf, 2 * hp + 1);
    const uint4* hs = reinterpret_cast<const uint4*>(&g_h2h[(size_t)s_ * 512]);
    uint4 qa = hs[hp * 32 + m];
    uint4 qb = hs[hp * 32 + 16 + m];
    __half2* pa = reinterpret_cast<__half2*>(&qa);
    __half2* pb = reinterpret_cast<__half2*>(&qb);
    float r[8];
    #pragma unroll
    for (int i = 0; i < 4; i++) {
        float2 fa = __half22float2(pa[i]);
        float2 fb = __half22float2(pb[i]);
        r[2 * i]     = ca * fa.x + cb * fb.x;
        r[2 * i + 1] = ca * fa.y + cb * fb.y;
    }
    #pragma unroll
    for (int i = 0; i < 8; i++) r[i] += __shfl_xor_sync(0xffffffffu, r[i], 16);
    if (l < 16) {
        float* ab = &outp[(size_t)d_ * 128 + m * 8];
        red4(ab,     r[0], r[1], r[2], r[3]);
        red4(ab + 4, r[4], r[5], r[6], r[7]);
    }
}

// ---------------- host launch ----------------------------------------------------
extern "C" void kernel_launch(void* const* d_in, const int* in_sizes, int n_in,
                              void* d_out, int out_size) {
    const float* x      = (const float*)d_in[0];
    const int*   ei     = (const int*)  d_in[1];
    const int*   nt     = (const int*)  d_in[2];
    const float* ea     = (const float*)d_in[3];
    const int*   et     = (const int*)  d_in[4];
    const float* ne1    = (const float*)d_in[5];
    const float* w1     = (const float*)d_in[6];
    const float* we1    = (const float*)d_in[7];
    const float* asrc1  = (const float*)d_in[8];
    const float* adst1  = (const float*)d_in[9];
    const float* aedge1 = (const float*)d_in[10];
    const float* ee1    = (const float*)d_in[11];
    const float* wres1  = (const float*)d_in[12];
    const float* b1     = (const float*)d_in[13];
    const float* gamma  = (const float*)d_in[14];
    const float* beta   = (const float*)d_in[15];
    const float* ne2    = (const float*)d_in[16];
    const float* w2     = (const float*)d_in[17];
    const float* we2    = (const float*)d_in[18];
    const float* asrc2  = (const float*)d_in[19];
    const float* adst2  = (const float*)d_in[20];
    const float* aedge2 = (const float*)d_in[21];
    const float* ee2    = (const float*)d_in[22];
    const float* wres2  = (const float*)d_in[23];
    const float* b2     = (const float*)d_in[24];

    int N = in_sizes[0] / 32;
    int E = in_sizes[4];
    const int* src = ei;
    const int* dstp = ei + E;
    float* outp = (float*)d_out;

    // ---- precompute ----
    k_pre_a<<<10, 256>>>(we1, aedge1, we2, aedge2, ne1, w1, ne2, w2);
    k_pre_b<<<1, 32>>>(ee1, ee2);
    k_pre_w<<<352, 256>>>(w2, wres2, w1, wres1);

    // ---- layer 1 (tensor-core gemm1) ----
    size_t smem1 = 67584;
    cudaFuncSetAttribute(k_gemm1, cudaFuncAttributeMaxDynamicSharedMemorySize, (int)smem1);
    dim3 g1((N + 127) / 128, 2);
    k_gemm1<<<g1, 256, smem1>>>(x, nt, b1, asrc1, adst1, N);
    k_edge1<<<(E + 31) / 32, 256>>>(src, dstp, ea, et, E);

    // ---- batch norm ----
    k_bnstats<<<592, 128>>>(N);
    k_bnfin<<<1, 128>>>(gamma, beta, N);
    k_bnapply<<<(N * 16 + 255) / 256, 256>>>(N);

    // ---- layer 2 (tensor-core gemm2; ct=4 writes res2 into d_out) ----
    size_t smem2 = 69632;
    cudaFuncSetAttribute(k_gemm2, cudaFuncAttributeMaxDynamicSharedMemorySize, (int)smem2);
    dim3 g2((N + 127) / 128, 5);
    k_gemm2<<<g2, 256, smem2>>>(nt, b2, asrc2, adst2, outp, N);
    k_edge2A<<<(E * 4 + 255) / 256, 256>>>(src, dstp, E);
    k_aggr2<<<(E + 7) / 8, 256>>>(src, dstp, outp, E);
}